// round 3
// baseline (speedup 1.0000x reference)
#include <cuda_runtime.h>
#include <math.h>

// Problem constants
#define BATCH 8
#define NPTS 256
#define HD 128
#define BN (BATCH*NPTS)          // 2048 rows

// ---------------- scratch (device globals; no allocation allowed) ----------
__device__ float g_PA[BN*HD];    // h_i @ edg1_w[0:128]
__device__ float g_PB[BN*HD];    // h_j @ edg1_w[128:256]
__device__ float g_CA[BN*HD];    // h_i @ cor1_w[0:128]
__device__ float g_CB[BN*HD];    // h_j @ cor1_w[128:256]
__device__ float g_D2[BN*NPTS];  // |x_i - x_j|^2
__device__ float g_D02[BN*NPTS]; // |x0_i - x0_j|^2
__device__ float g_agg[BN*HD];   // mean_j e*m
__device__ float g_upd[BN*3];    // mean_j cw*shift*offdiag

__device__ __forceinline__ float sigm(float v) {
    return __fdividef(1.f, 1.f + __expf(-v));
}
__device__ __forceinline__ float siluf(float v) {
    return v * sigm(v);
}

__device__ __forceinline__ float warp_allreduce(float v) {
    v += __shfl_xor_sync(0xffffffffu, v, 16);
    v += __shfl_xor_sync(0xffffffffu, v, 8);
    v += __shfl_xor_sync(0xffffffffu, v, 4);
    v += __shfl_xor_sync(0xffffffffu, v, 2);
    v += __shfl_xor_sync(0xffffffffu, v, 1);
    return v;
}

// packed f32x2 FMA: acc += a * b (elementwise on 2 packed floats)
#define FMA2(acc, a, b) \
    asm volatile("fma.rn.f32x2 %0, %1, %2, %0;" : "+l"(acc) : "l"(a), "l"(b))

// ---------------- kernel 1: per-node projections (TI=8 rows/block) ---------
__global__ void __launch_bounds__(128) proj_kernel(
    const float* __restrict__ h,
    const float* __restrict__ e1w,
    const float* __restrict__ c1w)
{
    const int r0 = blockIdx.x * 8;
    const int t  = threadIdx.x;
    __shared__ float hs[8][HD];
    #pragma unroll
    for (int r = 0; r < 8; r++) hs[r][t] = h[(r0 + r) * HD + t];
    __syncthreads();

    float pa[8], pb[8], ca[8], cb[8];
    #pragma unroll
    for (int r = 0; r < 8; r++) { pa[r]=0.f; pb[r]=0.f; ca[r]=0.f; cb[r]=0.f; }

    for (int k = 0; k < HD; k++) {
        float wea = e1w[k * HD + t];
        float web = e1w[(HD + k) * HD + t];
        float wca = c1w[k * HD + t];
        float wcb = c1w[(HD + k) * HD + t];
        #pragma unroll
        for (int r = 0; r < 8; r++) {
            float hk = hs[r][k];
            pa[r] = fmaf(hk, wea, pa[r]);
            pb[r] = fmaf(hk, web, pb[r]);
            ca[r] = fmaf(hk, wca, ca[r]);
            cb[r] = fmaf(hk, wcb, cb[r]);
        }
    }
    #pragma unroll
    for (int r = 0; r < 8; r++) {
        int bi = r0 + r;
        g_PA[bi * HD + t] = pa[r];
        g_PB[bi * HD + t] = pb[r];
        g_CA[bi * HD + t] = ca[r];
        g_CB[bi * HD + t] = cb[r];
    }
}

// ---------------- kernel 2: pairwise squared distances ---------------------
__global__ void __launch_bounds__(256) dist_kernel(
    const float* __restrict__ x, const float* __restrict__ x0)
{
    int idx = blockIdx.x * 256 + threadIdx.x;     // < BN*NPTS
    int j = idx & 255;
    int bi = idx >> 8;                            // b*256 + i
    int b  = bi >> 8;
    const float* xi = x  + bi * 3;
    const float* xj = x  + (b * NPTS + j) * 3;
    float dx = xi[0]-xj[0], dy = xi[1]-xj[1], dz = xi[2]-xj[2];
    g_D2[idx] = dx*dx + dy*dy + dz*dz;
    const float* yi = x0 + bi * 3;
    const float* yj = x0 + (b * NPTS + j) * 3;
    float ex = yi[0]-yj[0], ey = yi[1]-yj[1], ez = yi[2]-yj[2];
    g_D02[idx] = ex*ex + ey*ey + ez*ez;
}

// ============================================================================
// Edge / Cor kernels: f32x2-packed register-tile GEMM.
// Block = 128 threads = 4 warps. Warp jg owns j-rows [jg*4, jg*4+4) of the
// 16-row j-tile and the full 128 t-columns (lane tq owns cols 4tq..4tq+3).
// t1 tile stored in smem DUPLICATED ({v,v} per element) so one ld.shared.v2.u64
// yields 2 k-steps of an FFMA2-ready broadcast operand. W2 column pairs are
// contiguous in gmem (L1-resident) -> ld.global.nc.v2.u64.
// ============================================================================

// GEMM inner loop: acc[jj*2+p] (f32x2) += t1[jj][k]*(W[k][c0+2p], W[k][c0+2p+1])
__device__ __forceinline__ void gemm_tile_f32x2(
    unsigned long long acc[8], const float* __restrict__ wbase,
    unsigned trow_addr)
{
    #pragma unroll 4
    for (int k = 0; k < HD; k += 2) {
        unsigned long long w00, w01, w10, w11;
        asm volatile("ld.global.nc.v2.u64 {%0,%1}, [%2];"
            : "=l"(w00), "=l"(w01) : "l"(wbase + (size_t)k * HD));
        asm volatile("ld.global.nc.v2.u64 {%0,%1}, [%2];"
            : "=l"(w10), "=l"(w11) : "l"(wbase + (size_t)(k + 1) * HD));
        #pragma unroll
        for (int jj = 0; jj < 4; jj++) {
            unsigned long long d0, d1;
            asm volatile("ld.shared.v2.u64 {%0,%1}, [%2];"
                : "=l"(d0), "=l"(d1) : "r"(trow_addr + (jj * HD + k) * 8));
            FMA2(acc[jj*2+0], d0, w00);
            FMA2(acc[jj*2+1], d0, w01);
            FMA2(acc[jj*2+0], d1, w10);
            FMA2(acc[jj*2+1], d1, w11);
        }
    }
}

// ---------------- kernel 3: edge chain -> g_agg ----------------------------
__global__ void __launch_bounds__(128, 8) edge_kernel(
    const float* __restrict__ e1w, const float* __restrict__ e1b,
    const float* __restrict__ e2w, const float* __restrict__ e2b,
    const float* __restrict__ eiw, const float* __restrict__ eib)
{
    __shared__ unsigned long long t1d[16 * HD];   // duplicated t1 tile (16 KB)
    __shared__ float d2s[16], d02s[16];
    __shared__ float aggPart[4 * HD];

    const int bi = blockIdx.x;
    const int b  = bi >> 8;
    const int i  = bi & 255;
    const int t  = threadIdx.x;
    const int tq = t & 31;          // lane: t-columns 4tq..4tq+3
    const int jg = t >> 5;          // warp: j-rows jg*4..jg*4+3
    const int c0 = 4 * tq;

    unsigned t1d_base;
    asm("{ .reg .u64 tmp; cvta.to.shared.u64 tmp, %1; cvt.u32.u64 %0, tmp; }"
        : "=r"(t1d_base) : "l"(t1d));
    const unsigned trow = t1d_base + (jg * 4 * HD) * 8;

    // producer constants (column = t)
    const float pak  = g_PA[bi * HD + t];
    const float w256 = e1w[256 * HD + t];
    const float w257 = e1w[257 * HD + t];
    const float b1   = e1b[t];
    // epilogue constants (columns c0..c0+3)
    float b2r[4], eiw4[4];
    #pragma unroll
    for (int c = 0; c < 4; c++) { b2r[c] = e2b[c0 + c]; eiw4[c] = eiw[c0 + c]; }
    const float bi0  = eib[0];
    const float* PBb = g_PB + (size_t)b * NPTS * HD;
    const float* wbase = e2w + c0;

    float aggP[4] = {0.f, 0.f, 0.f, 0.f};

    for (int j0 = 0; j0 < NPTS; j0 += 16) {
        __syncthreads();
        if (t < 16) {
            d2s[t]  = g_D2 [bi * NPTS + j0 + t];
            d02s[t] = g_D02[bi * NPTS + j0 + t];
        }
        __syncthreads();
        // producer: t1[jj][t], stored duplicated
        #pragma unroll
        for (int jj = 0; jj < 16; jj++) {
            float v = pak + __ldg(&PBb[(j0 + jj) * HD + t])
                    + d2s[jj] * w256 + d02s[jj] * w257 + b1;
            v = siluf(v);
            asm volatile("st.shared.v2.f32 [%0], {%1, %1};"
                :: "r"(t1d_base + (jj * HD + t) * 8), "f"(v));
        }
        __syncthreads();

        unsigned long long acc[8];
        #pragma unroll
        for (int q = 0; q < 8; q++) acc[q] = 0ULL;
        gemm_tile_f32x2(acc, wbase, trow);

        // m = silu(acc + b2) for this thread's 4x4 tile
        float m[16];
        #pragma unroll
        for (int jj = 0; jj < 4; jj++)
            #pragma unroll
            for (int p = 0; p < 2; p++) {
                float lo, hi;
                asm("mov.b64 {%0,%1}, %2;" : "=f"(lo), "=f"(hi) : "l"(acc[jj*2+p]));
                m[jj*4 + 2*p]     = siluf(lo + b2r[2*p]);
                m[jj*4 + 2*p + 1] = siluf(hi + b2r[2*p+1]);
            }
        // per j-row: e = sigmoid(<m, eiw> + eib), offdiag, agg += e*m
        #pragma unroll
        for (int jj = 0; jj < 4; jj++) {
            float loc = m[jj*4+0]*eiw4[0] + m[jj*4+1]*eiw4[1]
                      + m[jj*4+2]*eiw4[2] + m[jj*4+3]*eiw4[3];
            loc = warp_allreduce(loc);
            float e = sigm(loc + bi0);
            int j = j0 + jg * 4 + jj;
            if (j == i) e = 0.f;
            #pragma unroll
            for (int c = 0; c < 4; c++)
                aggP[c] = fmaf(e, m[jj*4+c], aggP[c]);
        }
    }
    // combine 4 warp-partials per column
    #pragma unroll
    for (int c = 0; c < 4; c++) aggPart[jg * HD + c0 + c] = aggP[c];
    __syncthreads();
    float s = aggPart[t] + aggPart[HD + t] + aggPart[2*HD + t] + aggPart[3*HD + t];
    g_agg[bi * HD + t] = s * (1.0f / 256.0f);
}

// ---------------- kernel 4: coordinate chain -> g_upd ----------------------
__global__ void __launch_bounds__(128, 8) cor_kernel(
    const float* __restrict__ c1w, const float* __restrict__ c1b,
    const float* __restrict__ c2w, const float* __restrict__ c2b,
    const float* __restrict__ c3w, const float* __restrict__ c3b,
    const float* __restrict__ x)
{
    __shared__ unsigned long long t1d[16 * HD];
    __shared__ float d2s[16], d02s[16];
    __shared__ float updPart[12];

    const int bi = blockIdx.x;
    const int b  = bi >> 8;
    const int i  = bi & 255;
    const int t  = threadIdx.x;
    const int tq = t & 31;
    const int jg = t >> 5;
    const int lane = tq;
    const int c0 = 4 * tq;

    unsigned t1d_base;
    asm("{ .reg .u64 tmp; cvta.to.shared.u64 tmp, %1; cvt.u32.u64 %0, tmp; }"
        : "=r"(t1d_base) : "l"(t1d));
    const unsigned trow = t1d_base + (jg * 4 * HD) * 8;

    const float cak  = g_CA[bi * HD + t];
    const float w256 = c1w[256 * HD + t];
    const float w257 = c1w[257 * HD + t];
    const float b1   = c1b[t];
    float b2r[4], w3v4[4];
    #pragma unroll
    for (int c = 0; c < 4; c++) { b2r[c] = c2b[c0 + c]; w3v4[c] = c3w[c0 + c]; }
    const float b3   = c3b[0];
    const float* CBb = g_CB + (size_t)b * NPTS * HD;
    const float* wbase = c2w + c0;

    const float xi0 = x[bi * 3 + 0];
    const float xi1 = x[bi * 3 + 1];
    const float xi2 = x[bi * 3 + 2];
    float ux = 0.f, uy = 0.f, uz = 0.f;

    for (int j0 = 0; j0 < NPTS; j0 += 16) {
        __syncthreads();
        if (t < 16) {
            d2s[t]  = g_D2 [bi * NPTS + j0 + t];
            d02s[t] = g_D02[bi * NPTS + j0 + t];
        }
        __syncthreads();
        #pragma unroll
        for (int jj = 0; jj < 16; jj++) {
            float v = cak + __ldg(&CBb[(j0 + jj) * HD + t])
                    + d2s[jj] * w256 + d02s[jj] * w257 + b1;
            v = siluf(v);
            asm volatile("st.shared.v2.f32 [%0], {%1, %1};"
                :: "r"(t1d_base + (jj * HD + t) * 8), "f"(v));
        }
        __syncthreads();

        unsigned long long acc[8];
        #pragma unroll
        for (int q = 0; q < 8; q++) acc[q] = 0ULL;
        gemm_tile_f32x2(acc, wbase, trow);

        #pragma unroll
        for (int jj = 0; jj < 4; jj++) {
            float c2v[4];
            #pragma unroll
            for (int p = 0; p < 2; p++) {
                float lo, hi;
                asm("mov.b64 {%0,%1}, %2;" : "=f"(lo), "=f"(hi) : "l"(acc[jj*2+p]));
                c2v[2*p]   = siluf(lo + b2r[2*p]);
                c2v[2*p+1] = siluf(hi + b2r[2*p+1]);
            }
            float loc = c2v[0]*w3v4[0] + c2v[1]*w3v4[1]
                      + c2v[2]*w3v4[2] + c2v[3]*w3v4[3];
            loc = warp_allreduce(loc);
            // lane jj of each warp applies the coordinate update for j-row jj
            if (lane == jj) {
                int jl = jg * 4 + jj;
                int j  = j0 + jl;
                if (j != i) {
                    float cw  = loc + b3;
                    float d2v = d2s[jl];
                    float dist = (d2v > 0.f) ? sqrtf(d2v) : 0.f;
                    float f = __fdividef(cw, dist + 1.f);
                    const float* xj = x + ((size_t)b * NPTS + j) * 3;
                    ux = fmaf(f, xi0 - xj[0], ux);
                    uy = fmaf(f, xi1 - xj[1], uy);
                    uz = fmaf(f, xi2 - xj[2], uz);
                }
            }
        }
    }
    // sum lanes 0..3 within each warp
    ux += __shfl_xor_sync(0xffffffffu, ux, 2);
    ux += __shfl_xor_sync(0xffffffffu, ux, 1);
    uy += __shfl_xor_sync(0xffffffffu, uy, 2);
    uy += __shfl_xor_sync(0xffffffffu, uy, 1);
    uz += __shfl_xor_sync(0xffffffffu, uz, 2);
    uz += __shfl_xor_sync(0xffffffffu, uz, 1);
    if (lane == 0) {
        updPart[jg * 3 + 0] = ux;
        updPart[jg * 3 + 1] = uy;
        updPart[jg * 3 + 2] = uz;
    }
    __syncthreads();
    if (t < 3) {
        float s = updPart[t] + updPart[3 + t] + updPart[6 + t] + updPart[9 + t];
        g_upd[bi * 3 + t] = s * (1.0f / 256.0f);
    }
}

// ---------------- kernel 5: node MLP + outputs (TI=8 rows/block) -----------
__global__ void __launch_bounds__(128) final_kernel(
    const float* __restrict__ hin, const float* __restrict__ xin,
    const float* __restrict__ pm,
    const float* __restrict__ n1w, const float* __restrict__ n1b,
    const float* __restrict__ n2w, const float* __restrict__ n2b,
    float* __restrict__ out)
{
    const int r0 = blockIdx.x * 8;
    const int t  = threadIdx.x;
    __shared__ float nin[8][256];
    __shared__ float tmid[8][HD];
    #pragma unroll
    for (int r = 0; r < 8; r++) {
        nin[r][t]       = hin[(r0 + r) * HD + t];
        nin[r][HD + t]  = g_agg[(r0 + r) * HD + t];
    }
    __syncthreads();
    float a[8];
    #pragma unroll
    for (int r = 0; r < 8; r++) a[r] = n1b[t];
    for (int k = 0; k < 256; k++) {
        float wv = n1w[k * HD + t];
        #pragma unroll
        for (int r = 0; r < 8; r++) a[r] = fmaf(nin[r][k], wv, a[r]);
    }
    #pragma unroll
    for (int r = 0; r < 8; r++) tmid[r][t] = siluf(a[r]);
    __syncthreads();
    #pragma unroll
    for (int r = 0; r < 8; r++) a[r] = n2b[t];
    for (int k = 0; k < HD; k++) {
        float wv = n2w[k * HD + t];
        #pragma unroll
        for (int r = 0; r < 8; r++) a[r] = fmaf(tmid[r][k], wv, a[r]);
    }
    float* outx = out;                  // x_next: BN*3
    float* outh = out + BN * 3;         // h_next: BN*HD
    #pragma unroll
    for (int r = 0; r < 8; r++) {
        int bi = r0 + r;
        float mask = pm[bi];
        outh[bi * HD + t] = (nin[r][t] + a[r]) * mask;
        if (t < 3) outx[bi * 3 + t] = (xin[bi * 3 + t] + g_upd[bi * 3 + t]) * mask;
    }
}

// ---------------- launch ----------------------------------------------------
extern "C" void kernel_launch(void* const* d_in, const int* in_sizes, int n_in,
                              void* d_out, int out_size)
{
    const float* x   = (const float*)d_in[0];
    const float* h   = (const float*)d_in[1];
    const float* x0  = (const float*)d_in[2];
    const float* pm  = (const float*)d_in[3];
    const float* e1w = (const float*)d_in[4];
    const float* e1b = (const float*)d_in[5];
    const float* e2w = (const float*)d_in[6];
    const float* e2b = (const float*)d_in[7];
    const float* eiw = (const float*)d_in[8];
    const float* eib = (const float*)d_in[9];
    const float* n1w = (const float*)d_in[10];
    const float* n1b = (const float*)d_in[11];
    const float* n2w = (const float*)d_in[12];
    const float* n2b = (const float*)d_in[13];
    const float* c1w = (const float*)d_in[14];
    const float* c1b = (const float*)d_in[15];
    const float* c2w = (const float*)d_in[16];
    const float* c2b = (const float*)d_in[17];
    const float* c3w = (const float*)d_in[18];
    const float* c3b = (const float*)d_in[19];
    float* out = (float*)d_out;

    proj_kernel<<<BN / 8, 128>>>(h, e1w, c1w);
    dist_kernel<<<(BN * NPTS) / 256, 256>>>(x, x0);
    edge_kernel<<<BN, 128>>>(e1w, e1b, e2w, e2b, eiw, eib);
    cor_kernel<<<BN, 128>>>(c1w, c1b, c2w, c2b, c3w, c3b, x);
    final_kernel<<<BN / 8, 128>>>(h, x, pm, n1w, n1b, n2w, n2b, out);
}

// round 5
// speedup vs baseline: 2.5999x; 2.5999x over previous
#include <cuda_runtime.h>
#include <cuda_bf16.h>
#include <math.h>
#include <stdint.h>

// Problem constants
#define BATCH 8
#define NPTS 256
#define HD 128
#define BN (BATCH*NPTS)          // 2048 rows
#define BSTRIDE 136              // padded row stride (bf16 elems) for ldmatrix
#define TILE_BYTES (128*BSTRIDE*2)   // 34816 per bf16 tile

// ---------------- scratch (device globals; no allocation allowed) ----------
__device__ float g_PA[BN*HD];
__device__ float g_PB[BN*HD];
__device__ float g_CA[BN*HD];
__device__ float g_CB[BN*HD];
__device__ float g_D2[BN*NPTS];
__device__ float g_D02[BN*NPTS];
__device__ float g_agg[BN*HD];
__device__ float g_upd[BN*3];
// W2^T hi/lo in padded [n][k] bf16 layout (prep_kernel fills)
__device__ __align__(16) __nv_bfloat16 g_eBhi[128*BSTRIDE];
__device__ __align__(16) __nv_bfloat16 g_eBlo[128*BSTRIDE];
__device__ __align__(16) __nv_bfloat16 g_cBhi[128*BSTRIDE];
__device__ __align__(16) __nv_bfloat16 g_cBlo[128*BSTRIDE];

__device__ __forceinline__ float sigm(float v) {
    return __fdividef(1.f, 1.f + __expf(-v));
}
__device__ __forceinline__ float siluf(float v) {
    return v * sigm(v);
}

__device__ __forceinline__ uint32_t smem_u32(const void* p) {
    uint32_t a;
    asm("{ .reg .u64 tmp; cvta.to.shared.u64 tmp, %1; cvt.u32.u64 %0, tmp; }"
        : "=r"(a) : "l"(p));
    return a;
}

__device__ __forceinline__ void ldsm4(uint32_t r[4], uint32_t addr) {
    asm volatile("ldmatrix.sync.aligned.m8n8.x4.shared.b16 {%0,%1,%2,%3}, [%4];"
        : "=r"(r[0]), "=r"(r[1]), "=r"(r[2]), "=r"(r[3]) : "r"(addr));
}

__device__ __forceinline__ void mma_bf16(float d[4], const uint32_t a[4],
                                         const uint32_t b0, const uint32_t b1) {
    asm volatile(
        "mma.sync.aligned.m16n8k16.row.col.f32.bf16.bf16.f32 "
        "{%0,%1,%2,%3}, {%4,%5,%6,%7}, {%8,%9}, {%0,%1,%2,%3};"
        : "+f"(d[0]), "+f"(d[1]), "+f"(d[2]), "+f"(d[3])
        : "r"(a[0]), "r"(a[1]), "r"(a[2]), "r"(a[3]), "r"(b0), "r"(b1));
}

// ---------------- kernel 0: prep W2^T hi/lo padded tiles -------------------
__global__ void __launch_bounds__(128) prep_kernel(
    const float* __restrict__ e2w, const float* __restrict__ c2w)
{
    int n = blockIdx.x;        // output feature (B "row")
    int k = threadIdx.x;       // K
    int idx = n * BSTRIDE + k;
    float v = e2w[k * HD + n];
    __nv_bfloat16 h = __float2bfloat16(v);
    g_eBhi[idx] = h;
    g_eBlo[idx] = __float2bfloat16(v - __bfloat162float(h));
    v = c2w[k * HD + n];
    h = __float2bfloat16(v);
    g_cBhi[idx] = h;
    g_cBlo[idx] = __float2bfloat16(v - __bfloat162float(h));
}

// ---------------- kernel 1: per-node projections ---------------------------
__global__ void __launch_bounds__(128) proj_kernel(
    const float* __restrict__ h,
    const float* __restrict__ e1w,
    const float* __restrict__ c1w)
{
    const int r0 = blockIdx.x * 8;
    const int t  = threadIdx.x;
    __shared__ float hs[8][HD];
    #pragma unroll
    for (int r = 0; r < 8; r++) hs[r][t] = h[(r0 + r) * HD + t];
    __syncthreads();

    float pa[8], pb[8], ca[8], cb[8];
    #pragma unroll
    for (int r = 0; r < 8; r++) { pa[r]=0.f; pb[r]=0.f; ca[r]=0.f; cb[r]=0.f; }

    for (int k = 0; k < HD; k++) {
        float wea = e1w[k * HD + t];
        float web = e1w[(HD + k) * HD + t];
        float wca = c1w[k * HD + t];
        float wcb = c1w[(HD + k) * HD + t];
        #pragma unroll
        for (int r = 0; r < 8; r++) {
            float hk = hs[r][k];
            pa[r] = fmaf(hk, wea, pa[r]);
            pb[r] = fmaf(hk, web, pb[r]);
            ca[r] = fmaf(hk, wca, ca[r]);
            cb[r] = fmaf(hk, wcb, cb[r]);
        }
    }
    #pragma unroll
    for (int r = 0; r < 8; r++) {
        int bi = r0 + r;
        g_PA[bi * HD + t] = pa[r];
        g_PB[bi * HD + t] = pb[r];
        g_CA[bi * HD + t] = ca[r];
        g_CB[bi * HD + t] = cb[r];
    }
}

// ---------------- kernel 2: pairwise squared distances ---------------------
__global__ void __launch_bounds__(256) dist_kernel(
    const float* __restrict__ x, const float* __restrict__ x0)
{
    int idx = blockIdx.x * 256 + threadIdx.x;
    int j = idx & 255;
    int bi = idx >> 8;
    int b  = bi >> 8;
    const float* xi = x  + bi * 3;
    const float* xj = x  + (b * NPTS + j) * 3;
    float dx = xi[0]-xj[0], dy = xi[1]-xj[1], dz = xi[2]-xj[2];
    g_D2[idx] = dx*dx + dy*dy + dz*dz;
    const float* yi = x0 + bi * 3;
    const float* yj = x0 + (b * NPTS + j) * 3;
    float ex = yi[0]-yj[0], ey = yi[1]-yj[1], ez = yi[2]-yj[2];
    g_D02[idx] = ex*ex + ey*ey + ez*ez;
}

// ============================================================================
// smem layout (bytes):
//   [0            : 34816)   A hi tile (128 x 136 bf16)
//   [34816        : 69632)   A lo tile
//   [69632        : 104448)  B hi tile
//   [104448       : 139264)  B lo tile
//   [139264       : ...)     ext float scratch
// ============================================================================
#define OFF_ALO  34816
#define OFF_BHI  69632
#define OFF_BLO  104448
#define OFF_EXT  139264
#define E_SMEM_TOTAL (OFF_EXT + 1920*4)
#define C_SMEM_TOTAL (OFF_EXT + 1152*4)

// producer: compute t1 rows for this warp, split bf16 hi/lo, store padded.
// warp w -> rows w*16..w*16+15; lane -> k = lane*4..lane*4+3.
__device__ __forceinline__ void produce_tile(
    int w, int lane, int j0,
    const float4 pab, const float4 w256_4, const float4 w257_4,
    const float* __restrict__ Pbase,
    const float* d2s, const float* d02s,
    uint32_t aHi32, uint32_t aLo32)
{
    const int k0 = lane * 4;
    #pragma unroll 4
    for (int rr = 0; rr < 16; rr++) {
        int row = w * 16 + rr;
        const float4 pb4 = *reinterpret_cast<const float4*>(
            &Pbase[(size_t)(j0 + row) * HD + k0]);
        float dj = d2s[row], d0j = d02s[row];
        float v0 = siluf(pab.x + pb4.x + dj * w256_4.x + d0j * w257_4.x);
        float v1 = siluf(pab.y + pb4.y + dj * w256_4.y + d0j * w257_4.y);
        float v2 = siluf(pab.z + pb4.z + dj * w256_4.z + d0j * w257_4.z);
        float v3 = siluf(pab.w + pb4.w + dj * w256_4.w + d0j * w257_4.w);
        __nv_bfloat16 h0 = __float2bfloat16(v0);
        __nv_bfloat16 h1 = __float2bfloat16(v1);
        __nv_bfloat16 h2 = __float2bfloat16(v2);
        __nv_bfloat16 h3 = __float2bfloat16(v3);
        __nv_bfloat162 H01 = __halves2bfloat162(h0, h1);
        __nv_bfloat162 H23 = __halves2bfloat162(h2, h3);
        __nv_bfloat162 L01 = __halves2bfloat162(
            __float2bfloat16(v0 - __bfloat162float(h0)),
            __float2bfloat16(v1 - __bfloat162float(h1)));
        __nv_bfloat162 L23 = __halves2bfloat162(
            __float2bfloat16(v2 - __bfloat162float(h2)),
            __float2bfloat16(v3 - __bfloat162float(h3)));
        uint32_t off = row * (BSTRIDE * 2) + lane * 8;
        asm volatile("st.shared.v2.b32 [%0], {%1, %2};"
            :: "r"(aHi32 + off),
               "r"(*reinterpret_cast<uint32_t*>(&H01)),
               "r"(*reinterpret_cast<uint32_t*>(&H23)) : "memory");
        asm volatile("st.shared.v2.b32 [%0], {%1, %2};"
            :: "r"(aLo32 + off),
               "r"(*reinterpret_cast<uint32_t*>(&L01)),
               "r"(*reinterpret_cast<uint32_t*>(&L23)) : "memory");
    }
}

// warp GEMM: 3-pass bf16 split, acc[16][4] fp32.
// warp tile: rows mrow0..+32, cols ncol0..+64.
__device__ __forceinline__ void gemm_warp(
    float acc[16][4], int mrow0, int ncol0, int lane,
    uint32_t aHi32, uint32_t aLo32, uint32_t bHi32, uint32_t bLo32)
{
    // ldmatrix lane->address offsets
    uint32_t aoff[2], boff[4];
    {
        int arow = (lane & 15);
        int akp  = (lane >> 4) * 8;
        #pragma unroll
        for (int mi = 0; mi < 2; mi++)
            aoff[mi] = (mrow0 + mi * 16 + arow) * (BSTRIDE * 2) + akp * 2;
        int bn = (lane & 7) + ((lane >> 4) & 1) * 8;
        int bkp = ((lane >> 3) & 1) * 8;
        #pragma unroll
        for (int nb = 0; nb < 4; nb++)
            boff[nb] = (ncol0 + nb * 16 + bn) * (BSTRIDE * 2) + bkp * 2;
    }
    #pragma unroll
    for (int ks = 0; ks < 8; ks++) {
        const uint32_t kb = ks * 32;   // 16 bf16 = 32 bytes
        uint32_t ah[2][4], al[2][4], bh[4][4], bl[4][4];
        #pragma unroll
        for (int mi = 0; mi < 2; mi++) {
            ldsm4(ah[mi], aHi32 + aoff[mi] + kb);
            ldsm4(al[mi], aLo32 + aoff[mi] + kb);
        }
        #pragma unroll
        for (int nb = 0; nb < 4; nb++) {
            ldsm4(bh[nb], bHi32 + boff[nb] + kb);
            ldsm4(bl[nb], bLo32 + boff[nb] + kb);
        }
        #pragma unroll
        for (int mi = 0; mi < 2; mi++)
            #pragma unroll
            for (int nb = 0; nb < 4; nb++) {
                mma_bf16(acc[mi*8 + 2*nb],     ah[mi], bh[nb][0], bh[nb][1]);
                mma_bf16(acc[mi*8 + 2*nb + 1], ah[mi], bh[nb][2], bh[nb][3]);
                mma_bf16(acc[mi*8 + 2*nb],     ah[mi], bl[nb][0], bl[nb][1]);
                mma_bf16(acc[mi*8 + 2*nb + 1], ah[mi], bl[nb][2], bl[nb][3]);
                mma_bf16(acc[mi*8 + 2*nb],     al[mi], bh[nb][0], bh[nb][1]);
                mma_bf16(acc[mi*8 + 2*nb + 1], al[mi], bh[nb][2], bh[nb][3]);
            }
    }
}

// ---------------- kernel 3: edge chain -> g_agg ----------------------------
__global__ void __launch_bounds__(256) edge_kernel(
    const float* __restrict__ e1w, const float* __restrict__ e1b,
    const float* __restrict__ e2b,
    const float* __restrict__ eiw, const float* __restrict__ eib)
{
    extern __shared__ __align__(16) unsigned char smem[];
    float* ext  = (float*)(smem + OFF_EXT);
    float* d2s  = ext;        float* d02s = ext + 128;
    float* b2s  = ext + 256;  float* eiws = ext + 384;
    float* dotP = ext + 512;  // 256
    float* e_s  = ext + 768;  // 128
    float* aggW = ext + 896;  // 8*128

    const uint32_t smem32 = smem_u32(smem);
    const uint32_t aHi32 = smem32, aLo32 = smem32 + OFF_ALO;
    const uint32_t bHi32 = smem32 + OFF_BHI, bLo32 = smem32 + OFF_BLO;

    const int bi = blockIdx.x;
    const int b  = bi >> 8;
    const int i  = bi & 255;
    const int t  = threadIdx.x;
    const int lane = t & 31, w = t >> 5;
    const int s = lane & 3, q = lane >> 2;
    const int mrow0 = (w & 3) * 32, ncol0 = (w >> 2) * 64;

    // load B tiles + per-col constants
    {
        const uint4* srcH = (const uint4*)g_eBhi;
        const uint4* srcL = (const uint4*)g_eBlo;
        uint4* dstH = (uint4*)(smem + OFF_BHI);
        uint4* dstL = (uint4*)(smem + OFF_BLO);
        for (int idx = t; idx < TILE_BYTES/16; idx += 256) {
            dstH[idx] = srcH[idx];
            dstL[idx] = srcL[idx];
        }
    }
    if (t < 128) { b2s[t] = e2b[t]; eiws[t] = eiw[t]; }

    // producer constants (k = lane*4..+3)
    const int k0 = lane * 4;
    float4 pab = *reinterpret_cast<const float4*>(&g_PA[bi * HD + k0]);
    const float4 b1_4 = *reinterpret_cast<const float4*>(&e1b[k0]);
    pab.x += b1_4.x; pab.y += b1_4.y; pab.z += b1_4.z; pab.w += b1_4.w;
    const float4 w256_4 = *reinterpret_cast<const float4*>(&e1w[256 * HD + k0]);
    const float4 w257_4 = *reinterpret_cast<const float4*>(&e1w[257 * HD + k0]);
    const float bi0 = eib[0];
    const float* PBb = g_PB + (size_t)b * NPTS * HD;

    float aggacc[16];
    #pragma unroll
    for (int c = 0; c < 16; c++) aggacc[c] = 0.f;

    for (int half = 0; half < 2; half++) {
        const int j0 = half << 7;
        if (t < 128) {
            d2s[t]  = g_D2 [bi * NPTS + j0 + t];
            d02s[t] = g_D02[bi * NPTS + j0 + t];
        }
        __syncthreads();
        produce_tile(w, lane, j0, pab, w256_4, w257_4, PBb, d2s, d02s,
                     aHi32, aLo32);
        __syncthreads();

        float acc[16][4];
        #pragma unroll
        for (int a = 0; a < 16; a++)
            #pragma unroll
            for (int e = 0; e < 4; e++) acc[a][e] = 0.f;
        gemm_warp(acc, mrow0, ncol0, lane, aHi32, aLo32, bHi32, bLo32);

        // m = silu(D + b2) in regs; per-row dots
        #pragma unroll
        for (int mi = 0; mi < 2; mi++) {
            float dot0 = 0.f, dot1 = 0.f;
            #pragma unroll
            for (int ni = 0; ni < 8; ni++) {
                int c0 = ncol0 + ni * 8 + 2 * s;
                float b2a = b2s[c0], b2b = b2s[c0 + 1];
                float* A = acc[mi*8 + ni];
                A[0] = siluf(A[0] + b2a); A[1] = siluf(A[1] + b2b);
                A[2] = siluf(A[2] + b2a); A[3] = siluf(A[3] + b2b);
                float ea = eiws[c0], eb = eiws[c0 + 1];
                dot0 += A[0]*ea + A[1]*eb;
                dot1 += A[2]*ea + A[3]*eb;
            }
            dot0 += __shfl_xor_sync(0xffffffffu, dot0, 1);
            dot0 += __shfl_xor_sync(0xffffffffu, dot0, 2);
            dot1 += __shfl_xor_sync(0xffffffffu, dot1, 1);
            dot1 += __shfl_xor_sync(0xffffffffu, dot1, 2);
            if (s == 0) {
                int r0 = mrow0 + mi * 16 + q;
                dotP[(w >> 2) * 128 + r0]     = dot0;
                dotP[(w >> 2) * 128 + r0 + 8] = dot1;
            }
        }
        __syncthreads();
        if (t < 128) {
            float sv = dotP[t] + dotP[128 + t] + bi0;
            float e = sigm(sv);
            if (j0 + t == i) e = 0.f;
            e_s[t] = e;
        }
        __syncthreads();
        // agg from fragments: aggacc[col-local] += e[row] * m
        #pragma unroll
        for (int mi = 0; mi < 2; mi++) {
            #pragma unroll
            for (int ni = 0; ni < 8; ni++) {
                int r0 = mrow0 + mi * 16 + q;
                float e0 = e_s[r0], e1 = e_s[r0 + 8];
                float* A = acc[mi*8 + ni];
                aggacc[ni*2+0] = fmaf(e0, A[0], fmaf(e1, A[2], aggacc[ni*2+0]));
                aggacc[ni*2+1] = fmaf(e0, A[1], fmaf(e1, A[3], aggacc[ni*2+1]));
            }
        }
        __syncthreads();
    }
    // reduce aggacc over q-lanes (cols depend only on s)
    #pragma unroll
    for (int c = 0; c < 16; c++) {
        float v = aggacc[c];
        v += __shfl_xor_sync(0xffffffffu, v, 4);
        v += __shfl_xor_sync(0xffffffffu, v, 8);
        v += __shfl_xor_sync(0xffffffffu, v, 16);
        aggacc[c] = v;
    }
    if (q == 0) {
        #pragma unroll
        for (int ni = 0; ni < 8; ni++) {
            aggW[w * 128 + ncol0 + ni * 8 + 2 * s]     = aggacc[ni*2+0];
            aggW[w * 128 + ncol0 + ni * 8 + 2 * s + 1] = aggacc[ni*2+1];
        }
    }
    __syncthreads();
    if (t < 128) {
        int g0 = (t >= 64) ? 4 : 0;
        float sv = aggW[g0*128 + t] + aggW[(g0+1)*128 + t]
                 + aggW[(g0+2)*128 + t] + aggW[(g0+3)*128 + t];
        g_agg[bi * HD + t] = sv * (1.0f / 256.0f);
    }
}

// ---------------- kernel 4: coordinate chain -> g_upd ----------------------
__global__ void __launch_bounds__(256) cor_kernel(
    const float* __restrict__ c1w, const float* __restrict__ c1b,
    const float* __restrict__ c2b,
    const float* __restrict__ c3w, const float* __restrict__ c3b,
    const float* __restrict__ x)
{
    extern __shared__ __align__(16) unsigned char smem[];
    float* ext  = (float*)(smem + OFF_EXT);
    float* d2s  = ext;        float* d02s = ext + 128;
    float* b2s  = ext + 256;  float* c3ws = ext + 384;
    float* dotP = ext + 512;  // 256
    float* updx = ext + 768;  float* updy = ext + 896;  float* updz = ext + 1024;

    const uint32_t smem32 = smem_u32(smem);
    const uint32_t aHi32 = smem32, aLo32 = smem32 + OFF_ALO;
    const uint32_t bHi32 = smem32 + OFF_BHI, bLo32 = smem32 + OFF_BLO;

    const int bi = blockIdx.x;
    const int b  = bi >> 8;
    const int i  = bi & 255;
    const int t  = threadIdx.x;
    const int lane = t & 31, w = t >> 5;
    const int s = lane & 3, q = lane >> 2;
    const int mrow0 = (w & 3) * 32, ncol0 = (w >> 2) * 64;

    {
        const uint4* srcH = (const uint4*)g_cBhi;
        const uint4* srcL = (const uint4*)g_cBlo;
        uint4* dstH = (uint4*)(smem + OFF_BHI);
        uint4* dstL = (uint4*)(smem + OFF_BLO);
        for (int idx = t; idx < TILE_BYTES/16; idx += 256) {
            dstH[idx] = srcH[idx];
            dstL[idx] = srcL[idx];
        }
    }
    if (t < 128) { b2s[t] = c2b[t]; c3ws[t] = c3w[t]; }

    const int k0 = lane * 4;
    float4 pab = *reinterpret_cast<const float4*>(&g_CA[bi * HD + k0]);
    const float4 b1_4 = *reinterpret_cast<const float4*>(&c1b[k0]);
    pab.x += b1_4.x; pab.y += b1_4.y; pab.z += b1_4.z; pab.w += b1_4.w;
    const float4 w256_4 = *reinterpret_cast<const float4*>(&c1w[256 * HD + k0]);
    const float4 w257_4 = *reinterpret_cast<const float4*>(&c1w[257 * HD + k0]);
    const float b3 = c3b[0];
    const float* CBb = g_CB + (size_t)b * NPTS * HD;

    const float xi0 = x[bi * 3 + 0];
    const float xi1 = x[bi * 3 + 1];
    const float xi2 = x[bi * 3 + 2];
    float ux = 0.f, uy = 0.f, uz = 0.f;

    for (int half = 0; half < 2; half++) {
        const int j0 = half << 7;
        if (t < 128) {
            d2s[t]  = g_D2 [bi * NPTS + j0 + t];
            d02s[t] = g_D02[bi * NPTS + j0 + t];
        }
        __syncthreads();
        produce_tile(w, lane, j0, pab, w256_4, w257_4, CBb, d2s, d02s,
                     aHi32, aLo32);
        __syncthreads();

        float acc[16][4];
        #pragma unroll
        for (int a = 0; a < 16; a++)
            #pragma unroll
            for (int e = 0; e < 4; e++) acc[a][e] = 0.f;
        gemm_warp(acc, mrow0, ncol0, lane, aHi32, aLo32, bHi32, bLo32);

        #pragma unroll
        for (int mi = 0; mi < 2; mi++) {
            float dot0 = 0.f, dot1 = 0.f;
            #pragma unroll
            for (int ni = 0; ni < 8; ni++) {
                int c0 = ncol0 + ni * 8 + 2 * s;
                float b2a = b2s[c0], b2b = b2s[c0 + 1];
                float* A = acc[mi*8 + ni];
                float m0 = siluf(A[0] + b2a), m1 = siluf(A[1] + b2b);
                float m2 = siluf(A[2] + b2a), m3 = siluf(A[3] + b2b);
                float wa = c3ws[c0], wb = c3ws[c0 + 1];
                dot0 += m0*wa + m1*wb;
                dot1 += m2*wa + m3*wb;
            }
            dot0 += __shfl_xor_sync(0xffffffffu, dot0, 1);
            dot0 += __shfl_xor_sync(0xffffffffu, dot0, 2);
            dot1 += __shfl_xor_sync(0xffffffffu, dot1, 1);
            dot1 += __shfl_xor_sync(0xffffffffu, dot1, 2);
            if (s == 0) {
                int r0 = mrow0 + mi * 16 + q;
                dotP[(w >> 2) * 128 + r0]     = dot0;
                dotP[(w >> 2) * 128 + r0 + 8] = dot1;
            }
        }
        __syncthreads();
        if (t < 128) {
            int j = j0 + t;
            if (j != i) {
                float cw = dotP[t] + dotP[128 + t] + b3;
                float d2v = d2s[t];
                float dist = (d2v > 0.f) ? sqrtf(d2v) : 0.f;
                float f = __fdividef(cw, dist + 1.f);
                const float* xj = x + ((size_t)b * NPTS + j) * 3;
                ux = fmaf(f, xi0 - xj[0], ux);
                uy = fmaf(f, xi1 - xj[1], uy);
                uz = fmaf(f, xi2 - xj[2], uz);
            }
        }
        __syncthreads();
    }
    if (t < 128) { updx[t] = ux; updy[t] = uy; updz[t] = uz; }
    __syncthreads();
    if (t < 3) {
        const float* arr = (t == 0) ? updx : (t == 1) ? updy : updz;
        float sv = 0.f;
        for (int r = 0; r < 128; r++) sv += arr[r];
        g_upd[bi * 3 + t] = sv * (1.0f / 256.0f);
    }
}

// ---------------- kernel 5: node MLP + outputs -----------------------------
__global__ void __launch_bounds__(128) final_kernel(
    const float* __restrict__ hin, const float* __restrict__ xin,
    const float* __restrict__ pm,
    const float* __restrict__ n1w, const float* __restrict__ n1b,
    const float* __restrict__ n2w, const float* __restrict__ n2b,
    float* __restrict__ out)
{
    const int r0 = blockIdx.x * 8;
    const int t  = threadIdx.x;
    __shared__ float nin[8][256];
    __shared__ float tmid[8][HD];
    #pragma unroll
    for (int r = 0; r < 8; r++) {
        nin[r][t]       = hin[(r0 + r) * HD + t];
        nin[r][HD + t]  = g_agg[(r0 + r) * HD + t];
    }
    __syncthreads();
    float a[8];
    #pragma unroll
    for (int r = 0; r < 8; r++) a[r] = n1b[t];
    for (int k = 0; k < 256; k++) {
        float wv = n1w[k * HD + t];
        #pragma unroll
        for (int r = 0; r < 8; r++) a[r] = fmaf(nin[r][k], wv, a[r]);
    }
    #pragma unroll
    for (int r = 0; r < 8; r++) tmid[r][t] = siluf(a[r]);
    __syncthreads();
    #pragma unroll
    for (int r = 0; r < 8; r++) a[r] = n2b[t];
    for (int k = 0; k < HD; k++) {
        float wv = n2w[k * HD + t];
        #pragma unroll
        for (int r = 0; r < 8; r++) a[r] = fmaf(tmid[r][k], wv, a[r]);
    }
    float* outx = out;                  // x_next: BN*3
    float* outh = out + BN * 3;         // h_next: BN*HD
    #pragma unroll
    for (int r = 0; r < 8; r++) {
        int bi = r0 + r;
        float mask = pm[bi];
        outh[bi * HD + t] = (nin[r][t] + a[r]) * mask;
        if (t < 3) outx[bi * 3 + t] = (xin[bi * 3 + t] + g_upd[bi * 3 + t]) * mask;
    }
}

// ---------------- launch ----------------------------------------------------
extern "C" void kernel_launch(void* const* d_in, const int* in_sizes, int n_in,
                              void* d_out, int out_size)
{
    const float* x   = (const float*)d_in[0];
    const float* h   = (const float*)d_in[1];
    const float* x0  = (const float*)d_in[2];
    const float* pm  = (const float*)d_in[3];
    const float* e1w = (const float*)d_in[4];
    const float* e1b = (const float*)d_in[5];
    const float* e2w = (const float*)d_in[6];
    const float* e2b = (const float*)d_in[7];
    const float* eiw = (const float*)d_in[8];
    const float* eib = (const float*)d_in[9];
    const float* n1w = (const float*)d_in[10];
    const float* n1b = (const float*)d_in[11];
    const float* n2w = (const float*)d_in[12];
    const float* n2b = (const float*)d_in[13];
    const float* c1w = (const float*)d_in[14];
    const float* c1b = (const float*)d_in[15];
    const float* c2w = (const float*)d_in[16];
    const float* c2b = (const float*)d_in[17];
    const float* c3w = (const float*)d_in[18];
    const float* c3b = (const float*)d_in[19];
    float* out = (float*)d_out;

    cudaFuncSetAttribute(edge_kernel,
        cudaFuncAttributeMaxDynamicSharedMemorySize, E_SMEM_TOTAL);
    cudaFuncSetAttribute(cor_kernel,
        cudaFuncAttributeMaxDynamicSharedMemorySize, C_SMEM_TOTAL);

    prep_kernel<<<128, 128>>>(e2w, c2w);
    proj_kernel<<<BN / 8, 128>>>(h, e1w, c1w);
    dist_kernel<<<(BN * NPTS) / 256, 256>>>(x, x0);
    edge_kernel<<<BN, 256, E_SMEM_TOTAL>>>(e1w, e1b, e2b, eiw, eib);
    cor_kernel<<<BN, 256, C_SMEM_TOTAL>>>(c1w, c1b, c2b, c3w, c3b, x);
    final_kernel<<<BN / 8, 128>>>(h, x, pm, n1w, n1b, n2w, n2b, out);
}

// round 6
// speedup vs baseline: 3.2555x; 1.2522x over previous
#include <cuda_runtime.h>
#include <cuda_bf16.h>
#include <math.h>
#include <stdint.h>

// Problem constants
#define BATCH 8
#define NPTS 256
#define HD 128
#define BN (BATCH*NPTS)          // 2048 rows
#define BSTRIDE 136              // padded row stride (bf16 elems) for ldmatrix
#define JT 64                    // j-tile rows
#define BT_BYTES (128*BSTRIDE*2) // 34816 per B bf16 tile
#define AT_BYTES (JT*BSTRIDE*2)  // 17408 per A bf16 tile

// ---------------- scratch (device globals; no allocation allowed) ----------
__device__ float g_PA[BN*HD];
__device__ float g_PB[BN*HD];
__device__ float g_CA[BN*HD];
__device__ float g_CB[BN*HD];
__device__ float g_D2[BN*NPTS];
__device__ float g_D02[BN*NPTS];
__device__ float g_agg[BN*HD];
__device__ float g_upd[BN*3];
// W2^T hi/lo in padded [n][k] bf16 layout (prep_kernel fills)
__device__ __align__(16) __nv_bfloat16 g_eBhi[128*BSTRIDE];
__device__ __align__(16) __nv_bfloat16 g_eBlo[128*BSTRIDE];
__device__ __align__(16) __nv_bfloat16 g_cBhi[128*BSTRIDE];
__device__ __align__(16) __nv_bfloat16 g_cBlo[128*BSTRIDE];

__device__ __forceinline__ float sigm(float v) {
    return __fdividef(1.f, 1.f + __expf(-v));
}
__device__ __forceinline__ float siluf(float v) {
    return v * sigm(v);
}

__device__ __forceinline__ uint32_t smem_u32(const void* p) {
    uint32_t a;
    asm("{ .reg .u64 tmp; cvta.to.shared.u64 tmp, %1; cvt.u32.u64 %0, tmp; }"
        : "=r"(a) : "l"(p));
    return a;
}

__device__ __forceinline__ void ldsm4(uint32_t r[4], uint32_t addr) {
    asm volatile("ldmatrix.sync.aligned.m8n8.x4.shared.b16 {%0,%1,%2,%3}, [%4];"
        : "=r"(r[0]), "=r"(r[1]), "=r"(r[2]), "=r"(r[3]) : "r"(addr));
}

__device__ __forceinline__ void mma_bf16(float d[4], const uint32_t a[4],
                                         const uint32_t b0, const uint32_t b1) {
    asm volatile(
        "mma.sync.aligned.m16n8k16.row.col.f32.bf16.bf16.f32 "
        "{%0,%1,%2,%3}, {%4,%5,%6,%7}, {%8,%9}, {%0,%1,%2,%3};"
        : "+f"(d[0]), "+f"(d[1]), "+f"(d[2]), "+f"(d[3])
        : "r"(a[0]), "r"(a[1]), "r"(a[2]), "r"(a[3]), "r"(b0), "r"(b1));
}

// ---------------- kernel 0: prep W2^T hi/lo padded tiles -------------------
__global__ void __launch_bounds__(128) prep_kernel(
    const float* __restrict__ e2w, const float* __restrict__ c2w)
{
    int n = blockIdx.x;
    int k = threadIdx.x;
    int idx = n * BSTRIDE + k;
    float v = e2w[k * HD + n];
    __nv_bfloat16 h = __float2bfloat16(v);
    g_eBhi[idx] = h;
    g_eBlo[idx] = __float2bfloat16(v - __bfloat162float(h));
    v = c2w[k * HD + n];
    h = __float2bfloat16(v);
    g_cBhi[idx] = h;
    g_cBlo[idx] = __float2bfloat16(v - __bfloat162float(h));
}

// ---------------- kernel 1: per-node projections ---------------------------
__global__ void __launch_bounds__(128) proj_kernel(
    const float* __restrict__ h,
    const float* __restrict__ e1w,
    const float* __restrict__ c1w)
{
    const int r0 = blockIdx.x * 8;
    const int t  = threadIdx.x;
    __shared__ float hs[8][HD];
    #pragma unroll
    for (int r = 0; r < 8; r++) hs[r][t] = h[(r0 + r) * HD + t];
    __syncthreads();

    float pa[8], pb[8], ca[8], cb[8];
    #pragma unroll
    for (int r = 0; r < 8; r++) { pa[r]=0.f; pb[r]=0.f; ca[r]=0.f; cb[r]=0.f; }

    for (int k = 0; k < HD; k++) {
        float wea = e1w[k * HD + t];
        float web = e1w[(HD + k) * HD + t];
        float wca = c1w[k * HD + t];
        float wcb = c1w[(HD + k) * HD + t];
        #pragma unroll
        for (int r = 0; r < 8; r++) {
            float hk = hs[r][k];
            pa[r] = fmaf(hk, wea, pa[r]);
            pb[r] = fmaf(hk, web, pb[r]);
            ca[r] = fmaf(hk, wca, ca[r]);
            cb[r] = fmaf(hk, wcb, cb[r]);
        }
    }
    #pragma unroll
    for (int r = 0; r < 8; r++) {
        int bi = r0 + r;
        g_PA[bi * HD + t] = pa[r];
        g_PB[bi * HD + t] = pb[r];
        g_CA[bi * HD + t] = ca[r];
        g_CB[bi * HD + t] = cb[r];
    }
}

// ---------------- kernel 2: pairwise squared distances ---------------------
__global__ void __launch_bounds__(256) dist_kernel(
    const float* __restrict__ x, const float* __restrict__ x0)
{
    int idx = blockIdx.x * 256 + threadIdx.x;
    int j = idx & 255;
    int bi = idx >> 8;
    int b  = bi >> 8;
    const float* xi = x  + bi * 3;
    const float* xj = x  + (b * NPTS + j) * 3;
    float dx = xi[0]-xj[0], dy = xi[1]-xj[1], dz = xi[2]-xj[2];
    g_D2[idx] = dx*dx + dy*dy + dz*dz;
    const float* yi = x0 + bi * 3;
    const float* yj = x0 + (b * NPTS + j) * 3;
    float ex = yi[0]-yj[0], ey = yi[1]-yj[1], ez = yi[2]-yj[2];
    g_D02[idx] = ex*ex + ey*ey + ez*ez;
}

// ============================================================================
// smem layout (bytes):
//   [0              : 17408)   A hi tile (64 x 136 bf16)
//   [17408          : 34816)   A lo tile
//   [34816          : 69632)   B hi tile (128 x 136 bf16)
//   [69632          : 104448)  B lo tile
//   [104448         : ...)     ext float scratch
// ============================================================================
#define OFF_ALO  17408
#define OFF_BHI  34816
#define OFF_BLO  69632
#define OFF_EXT  104448
#define E_SMEM_TOTAL (OFF_EXT + 960*4)
#define C_SMEM_TOTAL (OFF_EXT + 832*4)

// producer: warp w -> local rows w*8..w*8+7; lane -> k = lane*4..lane*4+3.
__device__ __forceinline__ void produce_tile(
    int w, int lane, int j0,
    const float4 pab, const float4 w256_4, const float4 w257_4,
    const float* __restrict__ Pbase,
    const float* d2s, const float* d02s,
    uint32_t aHi32, uint32_t aLo32)
{
    const int k0 = lane * 4;
    #pragma unroll 4
    for (int rr = 0; rr < 8; rr++) {
        int row = w * 8 + rr;
        const float4 pb4 = *reinterpret_cast<const float4*>(
            &Pbase[(size_t)(j0 + row) * HD + k0]);
        float dj = d2s[row], d0j = d02s[row];
        float v0 = siluf(pab.x + pb4.x + dj * w256_4.x + d0j * w257_4.x);
        float v1 = siluf(pab.y + pb4.y + dj * w256_4.y + d0j * w257_4.y);
        float v2 = siluf(pab.z + pb4.z + dj * w256_4.z + d0j * w257_4.z);
        float v3 = siluf(pab.w + pb4.w + dj * w256_4.w + d0j * w257_4.w);
        __nv_bfloat16 h0 = __float2bfloat16(v0);
        __nv_bfloat16 h1 = __float2bfloat16(v1);
        __nv_bfloat16 h2 = __float2bfloat16(v2);
        __nv_bfloat16 h3 = __float2bfloat16(v3);
        __nv_bfloat162 H01 = __halves2bfloat162(h0, h1);
        __nv_bfloat162 H23 = __halves2bfloat162(h2, h3);
        __nv_bfloat162 L01 = __halves2bfloat162(
            __float2bfloat16(v0 - __bfloat162float(h0)),
            __float2bfloat16(v1 - __bfloat162float(h1)));
        __nv_bfloat162 L23 = __halves2bfloat162(
            __float2bfloat16(v2 - __bfloat162float(h2)),
            __float2bfloat16(v3 - __bfloat162float(h3)));
        uint32_t off = row * (BSTRIDE * 2) + lane * 8;
        asm volatile("st.shared.v2.b32 [%0], {%1, %2};"
            :: "r"(aHi32 + off),
               "r"(*reinterpret_cast<uint32_t*>(&H01)),
               "r"(*reinterpret_cast<uint32_t*>(&H23)) : "memory");
        asm volatile("st.shared.v2.b32 [%0], {%1, %2};"
            :: "r"(aLo32 + off),
               "r"(*reinterpret_cast<uint32_t*>(&L01)),
               "r"(*reinterpret_cast<uint32_t*>(&L23)) : "memory");
    }
}

// warp GEMM: 3-pass bf16 split; warp tile rows mrow0..+32, cols ncol0..+32.
// acc[8][4]: index mi*4 + ni (ni = 8-col group 0..3).
__device__ __forceinline__ void gemm_warp(
    float acc[8][4], int mrow0, int ncol0, int lane,
    uint32_t aHi32, uint32_t aLo32, uint32_t bHi32, uint32_t bLo32)
{
    uint32_t aoff[2], boff[2];
    {
        int arow = (lane & 15);
        int akp  = (lane >> 4) * 8;
        #pragma unroll
        for (int mi = 0; mi < 2; mi++)
            aoff[mi] = (mrow0 + mi * 16 + arow) * (BSTRIDE * 2) + akp * 2;
        int bn = (lane & 7) + ((lane >> 4) & 1) * 8;
        int bkp = ((lane >> 3) & 1) * 8;
        #pragma unroll
        for (int nb = 0; nb < 2; nb++)
            boff[nb] = (ncol0 + nb * 16 + bn) * (BSTRIDE * 2) + bkp * 2;
    }
    #pragma unroll
    for (int ks = 0; ks < 8; ks++) {
        const uint32_t kb = ks * 32;
        uint32_t ah[2][4], al[2][4], bh[2][4], bl[2][4];
        #pragma unroll
        for (int mi = 0; mi < 2; mi++) {
            ldsm4(ah[mi], aHi32 + aoff[mi] + kb);
            ldsm4(al[mi], aLo32 + aoff[mi] + kb);
        }
        #pragma unroll
        for (int nb = 0; nb < 2; nb++) {
            ldsm4(bh[nb], bHi32 + boff[nb] + kb);
            ldsm4(bl[nb], bLo32 + boff[nb] + kb);
        }
        #pragma unroll
        for (int mi = 0; mi < 2; mi++)
            #pragma unroll
            for (int nb = 0; nb < 2; nb++) {
                mma_bf16(acc[mi*4 + 2*nb],     ah[mi], bh[nb][0], bh[nb][1]);
                mma_bf16(acc[mi*4 + 2*nb + 1], ah[mi], bh[nb][2], bh[nb][3]);
                mma_bf16(acc[mi*4 + 2*nb],     ah[mi], bl[nb][0], bl[nb][1]);
                mma_bf16(acc[mi*4 + 2*nb + 1], ah[mi], bl[nb][2], bl[nb][3]);
                mma_bf16(acc[mi*4 + 2*nb],     al[mi], bh[nb][0], bh[nb][1]);
                mma_bf16(acc[mi*4 + 2*nb + 1], al[mi], bh[nb][2], bh[nb][3]);
            }
    }
}

// ---------------- kernel 3: edge chain -> g_agg ----------------------------
// ext floats: d2s[64] d02s[64] b2s[128] eiws[128] dotP[256] e_s[64] aggW[256]
__global__ void __launch_bounds__(256, 2) edge_kernel(
    const float* __restrict__ e1w, const float* __restrict__ e1b,
    const float* __restrict__ e2b,
    const float* __restrict__ eiw, const float* __restrict__ eib)
{
    extern __shared__ __align__(16) unsigned char smem[];
    float* ext  = (float*)(smem + OFF_EXT);
    float* d2s  = ext;        float* d02s = ext + 64;
    float* b2s  = ext + 128;  float* eiws = ext + 256;
    float* dotP = ext + 384;  // 4*64
    float* e_s  = ext + 640;  // 64
    float* aggW = ext + 704;  // 8*32

    const uint32_t smem32 = smem_u32(smem);
    const uint32_t aHi32 = smem32, aLo32 = smem32 + OFF_ALO;
    const uint32_t bHi32 = smem32 + OFF_BHI, bLo32 = smem32 + OFF_BLO;

    const int bi = blockIdx.x;
    const int b  = bi >> 8;
    const int i  = bi & 255;
    const int t  = threadIdx.x;
    const int lane = t & 31, w = t >> 5;
    const int s = lane & 3, q = lane >> 2;
    const int mrow0 = (w & 1) * 32, ncol0 = (w >> 1) * 32;

    {
        const uint4* srcH = (const uint4*)g_eBhi;
        const uint4* srcL = (const uint4*)g_eBlo;
        uint4* dstH = (uint4*)(smem + OFF_BHI);
        uint4* dstL = (uint4*)(smem + OFF_BLO);
        for (int idx = t; idx < BT_BYTES/16; idx += 256) {
            dstH[idx] = srcH[idx];
            dstL[idx] = srcL[idx];
        }
    }
    if (t < 128) { b2s[t] = e2b[t]; eiws[t] = eiw[t]; }

    const int k0 = lane * 4;
    float4 pab = *reinterpret_cast<const float4*>(&g_PA[bi * HD + k0]);
    const float4 b1_4 = *reinterpret_cast<const float4*>(&e1b[k0]);
    pab.x += b1_4.x; pab.y += b1_4.y; pab.z += b1_4.z; pab.w += b1_4.w;
    const float4 w256_4 = *reinterpret_cast<const float4*>(&e1w[256 * HD + k0]);
    const float4 w257_4 = *reinterpret_cast<const float4*>(&e1w[257 * HD + k0]);
    const float bi0 = eib[0];
    const float* PBb = g_PB + (size_t)b * NPTS * HD;

    float aggacc[8];
    #pragma unroll
    for (int c = 0; c < 8; c++) aggacc[c] = 0.f;

    for (int j0 = 0; j0 < NPTS; j0 += JT) {
        if (t < JT) {
            d2s[t]  = g_D2 [bi * NPTS + j0 + t];
            d02s[t] = g_D02[bi * NPTS + j0 + t];
        }
        __syncthreads();
        produce_tile(w, lane, j0, pab, w256_4, w257_4, PBb, d2s, d02s,
                     aHi32, aLo32);
        __syncthreads();

        float acc[8][4];
        #pragma unroll
        for (int a = 0; a < 8; a++)
            #pragma unroll
            for (int e = 0; e < 4; e++) acc[a][e] = 0.f;
        gemm_warp(acc, mrow0, ncol0, lane, aHi32, aLo32, bHi32, bLo32);

        // m = silu(D + b2) in regs; per-row dots with eiw
        #pragma unroll
        for (int mi = 0; mi < 2; mi++) {
            float dot0 = 0.f, dot1 = 0.f;
            #pragma unroll
            for (int ni = 0; ni < 4; ni++) {
                int c0 = ncol0 + ni * 8 + 2 * s;
                float b2a = b2s[c0], b2b = b2s[c0 + 1];
                float* A = acc[mi*4 + ni];
                A[0] = siluf(A[0] + b2a); A[1] = siluf(A[1] + b2b);
                A[2] = siluf(A[2] + b2a); A[3] = siluf(A[3] + b2b);
                float ea = eiws[c0], eb = eiws[c0 + 1];
                dot0 += A[0]*ea + A[1]*eb;
                dot1 += A[2]*ea + A[3]*eb;
            }
            dot0 += __shfl_xor_sync(0xffffffffu, dot0, 1);
            dot0 += __shfl_xor_sync(0xffffffffu, dot0, 2);
            dot1 += __shfl_xor_sync(0xffffffffu, dot1, 1);
            dot1 += __shfl_xor_sync(0xffffffffu, dot1, 2);
            if (s == 0) {
                int r0 = mrow0 + mi * 16 + q;
                dotP[(w >> 1) * JT + r0]     = dot0;
                dotP[(w >> 1) * JT + r0 + 8] = dot1;
            }
        }
        __syncthreads();
        if (t < JT) {
            float sv = dotP[t] + dotP[JT + t] + dotP[2*JT + t]
                     + dotP[3*JT + t] + bi0;
            float e = sigm(sv);
            if (j0 + t == i) e = 0.f;
            e_s[t] = e;
        }
        __syncthreads();
        #pragma unroll
        for (int mi = 0; mi < 2; mi++) {
            int r0 = mrow0 + mi * 16 + q;
            float e0 = e_s[r0], e1 = e_s[r0 + 8];
            #pragma unroll
            for (int ni = 0; ni < 4; ni++) {
                float* A = acc[mi*4 + ni];
                aggacc[ni*2+0] = fmaf(e0, A[0], fmaf(e1, A[2], aggacc[ni*2+0]));
                aggacc[ni*2+1] = fmaf(e0, A[1], fmaf(e1, A[3], aggacc[ni*2+1]));
            }
        }
        __syncthreads();
    }
    // reduce aggacc over q-lanes (cols depend only on s)
    #pragma unroll
    for (int c = 0; c < 8; c++) {
        float v = aggacc[c];
        v += __shfl_xor_sync(0xffffffffu, v, 4);
        v += __shfl_xor_sync(0xffffffffu, v, 8);
        v += __shfl_xor_sync(0xffffffffu, v, 16);
        aggacc[c] = v;
    }
    if (q == 0) {
        #pragma unroll
        for (int ni = 0; ni < 4; ni++) {
            aggW[w * 32 + ni * 8 + 2 * s]     = aggacc[ni*2+0];
            aggW[w * 32 + ni * 8 + 2 * s + 1] = aggacc[ni*2+1];
        }
    }
    __syncthreads();
    if (t < 128) {
        int cq = t >> 5, cl = t & 31;
        float sv = aggW[(2*cq) * 32 + cl] + aggW[(2*cq + 1) * 32 + cl];
        g_agg[bi * HD + t] = sv * (1.0f / 256.0f);
    }
}

// ---------------- kernel 4: coordinate chain -> g_upd ----------------------
// ext floats: d2s[64] d02s[64] b2s[128] c3ws[128] dotP[256] updx/y/z[64 each]
__global__ void __launch_bounds__(256, 2) cor_kernel(
    const float* __restrict__ c1w, const float* __restrict__ c1b,
    const float* __restrict__ c2b,
    const float* __restrict__ c3w, const float* __restrict__ c3b,
    const float* __restrict__ x)
{
    extern __shared__ __align__(16) unsigned char smem[];
    float* ext  = (float*)(smem + OFF_EXT);
    float* d2s  = ext;        float* d02s = ext + 64;
    float* b2s  = ext + 128;  float* c3ws = ext + 256;
    float* dotP = ext + 384;  // 4*64
    float* updx = ext + 640;  float* updy = ext + 704;  float* updz = ext + 768;

    const uint32_t smem32 = smem_u32(smem);
    const uint32_t aHi32 = smem32, aLo32 = smem32 + OFF_ALO;
    const uint32_t bHi32 = smem32 + OFF_BHI, bLo32 = smem32 + OFF_BLO;

    const int bi = blockIdx.x;
    const int b  = bi >> 8;
    const int i  = bi & 255;
    const int t  = threadIdx.x;
    const int lane = t & 31, w = t >> 5;
    const int s = lane & 3, q = lane >> 2;
    const int mrow0 = (w & 1) * 32, ncol0 = (w >> 1) * 32;

    {
        const uint4* srcH = (const uint4*)g_cBhi;
        const uint4* srcL = (const uint4*)g_cBlo;
        uint4* dstH = (uint4*)(smem + OFF_BHI);
        uint4* dstL = (uint4*)(smem + OFF_BLO);
        for (int idx = t; idx < BT_BYTES/16; idx += 256) {
            dstH[idx] = srcH[idx];
            dstL[idx] = srcL[idx];
        }
    }
    if (t < 128) { b2s[t] = c2b[t]; c3ws[t] = c3w[t]; }

    const int k0 = lane * 4;
    float4 pab = *reinterpret_cast<const float4*>(&g_CA[bi * HD + k0]);
    const float4 b1_4 = *reinterpret_cast<const float4*>(&c1b[k0]);
    pab.x += b1_4.x; pab.y += b1_4.y; pab.z += b1_4.z; pab.w += b1_4.w;
    const float4 w256_4 = *reinterpret_cast<const float4*>(&c1w[256 * HD + k0]);
    const float4 w257_4 = *reinterpret_cast<const float4*>(&c1w[257 * HD + k0]);
    const float b3 = c3b[0];
    const float* CBb = g_CB + (size_t)b * NPTS * HD;

    const float xi0 = x[bi * 3 + 0];
    const float xi1 = x[bi * 3 + 1];
    const float xi2 = x[bi * 3 + 2];
    float ux = 0.f, uy = 0.f, uz = 0.f;

    for (int j0 = 0; j0 < NPTS; j0 += JT) {
        if (t < JT) {
            d2s[t]  = g_D2 [bi * NPTS + j0 + t];
            d02s[t] = g_D02[bi * NPTS + j0 + t];
        }
        __syncthreads();
        produce_tile(w, lane, j0, pab, w256_4, w257_4, CBb, d2s, d02s,
                     aHi32, aLo32);
        __syncthreads();

        float acc[8][4];
        #pragma unroll
        for (int a = 0; a < 8; a++)
            #pragma unroll
            for (int e = 0; e < 4; e++) acc[a][e] = 0.f;
        gemm_warp(acc, mrow0, ncol0, lane, aHi32, aLo32, bHi32, bLo32);

        #pragma unroll
        for (int mi = 0; mi < 2; mi++) {
            float dot0 = 0.f, dot1 = 0.f;
            #pragma unroll
            for (int ni = 0; ni < 4; ni++) {
                int c0 = ncol0 + ni * 8 + 2 * s;
                float b2a = b2s[c0], b2b = b2s[c0 + 1];
                float* A = acc[mi*4 + ni];
                float m0 = siluf(A[0] + b2a), m1 = siluf(A[1] + b2b);
                float m2 = siluf(A[2] + b2a), m3 = siluf(A[3] + b2b);
                float wa = c3ws[c0], wb = c3ws[c0 + 1];
                dot0 += m0*wa + m1*wb;
                dot1 += m2*wa + m3*wb;
            }
            dot0 += __shfl_xor_sync(0xffffffffu, dot0, 1);
            dot0 += __shfl_xor_sync(0xffffffffu, dot0, 2);
            dot1 += __shfl_xor_sync(0xffffffffu, dot1, 1);
            dot1 += __shfl_xor_sync(0xffffffffu, dot1, 2);
            if (s == 0) {
                int r0 = mrow0 + mi * 16 + q;
                dotP[(w >> 1) * JT + r0]     = dot0;
                dotP[(w >> 1) * JT + r0 + 8] = dot1;
            }
        }
        __syncthreads();
        if (t < JT) {
            int j = j0 + t;
            if (j != i) {
                float cw = dotP[t] + dotP[JT + t] + dotP[2*JT + t]
                         + dotP[3*JT + t] + b3;
                float d2v = d2s[t];
                float dist = (d2v > 0.f) ? sqrtf(d2v) : 0.f;
                float f = __fdividef(cw, dist + 1.f);
                const float* xj = x + ((size_t)b * NPTS + j) * 3;
                ux = fmaf(f, xi0 - xj[0], ux);
                uy = fmaf(f, xi1 - xj[1], uy);
                uz = fmaf(f, xi2 - xj[2], uz);
            }
        }
        __syncthreads();
    }
    if (t < JT) { updx[t] = ux; updy[t] = uy; updz[t] = uz; }
    __syncthreads();
    if (t < 3) {
        const float* arr = (t == 0) ? updx : (t == 1) ? updy : updz;
        float sv = 0.f;
        for (int r = 0; r < JT; r++) sv += arr[r];
        g_upd[bi * 3 + t] = sv * (1.0f / 256.0f);
    }
}

// ---------------- kernel 5: node MLP + outputs -----------------------------
__global__ void __launch_bounds__(128) final_kernel(
    const float* __restrict__ hin, const float* __restrict__ xin,
    const float* __restrict__ pm,
    const float* __restrict__ n1w, const float* __restrict__ n1b,
    const float* __restrict__ n2w, const float* __restrict__ n2b,
    float* __restrict__ out)
{
    const int r0 = blockIdx.x * 8;
    const int t  = threadIdx.x;
    __shared__ float nin[8][256];
    __shared__ float tmid[8][HD];
    #pragma unroll
    for (int r = 0; r < 8; r++) {
        nin[r][t]       = hin[(r0 + r) * HD + t];
        nin[r][HD + t]  = g_agg[(r0 + r) * HD + t];
    }
    __syncthreads();
    float a[8];
    #pragma unroll
    for (int r = 0; r < 8; r++) a[r] = n1b[t];
    for (int k = 0; k < 256; k++) {
        float wv = n1w[k * HD + t];
        #pragma unroll
        for (int r = 0; r < 8; r++) a[r] = fmaf(nin[r][k], wv, a[r]);
    }
    #pragma unroll
    for (int r = 0; r < 8; r++) tmid[r][t] = siluf(a[r]);
    __syncthreads();
    #pragma unroll
    for (int r = 0; r < 8; r++) a[r] = n2b[t];
    for (int k = 0; k < HD; k++) {
        float wv = n2w[k * HD + t];
        #pragma unroll
        for (int r = 0; r < 8; r++) a[r] = fmaf(tmid[r][k], wv, a[r]);
    }
    float* outx = out;                  // x_next: BN*3
    float* outh = out + BN * 3;         // h_next: BN*HD
    #pragma unroll
    for (int r = 0; r < 8; r++) {
        int bi = r0 + r;
        float mask = pm[bi];
        outh[bi * HD + t] = (nin[r][t] + a[r]) * mask;
        if (t < 3) outx[bi * 3 + t] = (xin[bi * 3 + t] + g_upd[bi * 3 + t]) * mask;
    }
}

// ---------------- launch ----------------------------------------------------
extern "C" void kernel_launch(void* const* d_in, const int* in_sizes, int n_in,
                              void* d_out, int out_size)
{
    const float* x   = (const float*)d_in[0];
    const float* h   = (const float*)d_in[1];
    const float* x0  = (const float*)d_in[2];
    const float* pm  = (const float*)d_in[3];
    const float* e1w = (const float*)d_in[4];
    const float* e1b = (const float*)d_in[5];
    const float* e2w = (const float*)d_in[6];
    const float* e2b = (const float*)d_in[7];
    const float* eiw = (const float*)d_in[8];
    const float* eib = (const float*)d_in[9];
    const float* n1w = (const float*)d_in[10];
    const float* n1b = (const float*)d_in[11];
    const float* n2w = (const float*)d_in[12];
    const float* n2b = (const float*)d_in[13];
    const float* c1w = (const float*)d_in[14];
    const float* c1b = (const float*)d_in[15];
    const float* c2w = (const float*)d_in[16];
    const float* c2b = (const float*)d_in[17];
    const float* c3w = (const float*)d_in[18];
    const float* c3b = (const float*)d_in[19];
    float* out = (float*)d_out;

    cudaFuncSetAttribute(edge_kernel,
        cudaFuncAttributeMaxDynamicSharedMemorySize, E_SMEM_TOTAL);
    cudaFuncSetAttribute(cor_kernel,
        cudaFuncAttributeMaxDynamicSharedMemorySize, C_SMEM_TOTAL);

    prep_kernel<<<128, 128>>>(e2w, c2w);
    proj_kernel<<<BN / 8, 128>>>(h, e1w, c1w);
    dist_kernel<<<(BN * NPTS) / 256, 256>>>(x, x0);
    edge_kernel<<<BN, 256, E_SMEM_TOTAL>>>(e1w, e1b, e2b, eiw, eib);
    cor_kernel<<<BN, 256, C_SMEM_TOTAL>>>(c1w, c1b, c2b, c3w, c3b, x);
    final_kernel<<<BN / 8, 128>>>(h, x, pm, n1w, n1b, n2w, n2b, out);
}

// round 7
// speedup vs baseline: 3.2735x; 1.0055x over previous
#include <cuda_runtime.h>
#include <cuda_bf16.h>
#include <math.h>
#include <stdint.h>

// Problem constants
#define BATCH 8
#define NPTS 256
#define HD 128
#define BN (BATCH*NPTS)          // 2048 rows
#define BSTRIDE 136              // padded row stride (bf16 elems) for ldmatrix
#define JT 32                    // j-tile rows
#define BT_BYTES (128*BSTRIDE*2) // 34816 per B bf16 tile
#define ATH_BYTES (JT*BSTRIDE*2) // 8704 per A half (hi or lo)
#define ABUF_BYTES (2*ATH_BYTES) // 17408 per A buffer (hi+lo)

// ---------------- scratch (device globals; no allocation allowed) ----------
__device__ float g_PA[BN*HD];
__device__ float g_PB[BN*HD];
__device__ float g_CA[BN*HD];
__device__ float g_CB[BN*HD];
__device__ float g_D2[BN*NPTS];
__device__ float g_D02[BN*NPTS];
__device__ float g_agg[BN*HD];
__device__ float g_upd[BN*3];
// W2^T hi/lo in padded [n][k] bf16 layout (prep_kernel fills)
__device__ __align__(16) __nv_bfloat16 g_eBhi[128*BSTRIDE];
__device__ __align__(16) __nv_bfloat16 g_eBlo[128*BSTRIDE];
__device__ __align__(16) __nv_bfloat16 g_cBhi[128*BSTRIDE];
__device__ __align__(16) __nv_bfloat16 g_cBlo[128*BSTRIDE];

__device__ __forceinline__ float sigm(float v) {
    return __fdividef(1.f, 1.f + __expf(-v));
}
__device__ __forceinline__ float siluf(float v) {
    return v * sigm(v);
}

__device__ __forceinline__ uint32_t smem_u32(const void* p) {
    uint32_t a;
    asm("{ .reg .u64 tmp; cvta.to.shared.u64 tmp, %1; cvt.u32.u64 %0, tmp; }"
        : "=r"(a) : "l"(p));
    return a;
}

__device__ __forceinline__ void ldsm4(uint32_t r[4], uint32_t addr) {
    asm volatile("ldmatrix.sync.aligned.m8n8.x4.shared.b16 {%0,%1,%2,%3}, [%4];"
        : "=r"(r[0]), "=r"(r[1]), "=r"(r[2]), "=r"(r[3]) : "r"(addr));
}

__device__ __forceinline__ void mma_bf16(float d[4], const uint32_t a[4],
                                         const uint32_t b0, const uint32_t b1) {
    asm volatile(
        "mma.sync.aligned.m16n8k16.row.col.f32.bf16.bf16.f32 "
        "{%0,%1,%2,%3}, {%4,%5,%6,%7}, {%8,%9}, {%0,%1,%2,%3};"
        : "+f"(d[0]), "+f"(d[1]), "+f"(d[2]), "+f"(d[3])
        : "r"(a[0]), "r"(a[1]), "r"(a[2]), "r"(a[3]), "r"(b0), "r"(b1));
}

// ---------------- kernel 0: prep W2^T hi/lo padded tiles -------------------
__global__ void __launch_bounds__(128) prep_kernel(
    const float* __restrict__ e2w, const float* __restrict__ c2w)
{
    int n = blockIdx.x;
    int k = threadIdx.x;
    int idx = n * BSTRIDE + k;
    float v = e2w[k * HD + n];
    __nv_bfloat16 h = __float2bfloat16(v);
    g_eBhi[idx] = h;
    g_eBlo[idx] = __float2bfloat16(v - __bfloat162float(h));
    v = c2w[k * HD + n];
    h = __float2bfloat16(v);
    g_cBhi[idx] = h;
    g_cBlo[idx] = __float2bfloat16(v - __bfloat162float(h));
}

// ---------------- kernel 1: per-node projections ---------------------------
__global__ void __launch_bounds__(128) proj_kernel(
    const float* __restrict__ h,
    const float* __restrict__ e1w,
    const float* __restrict__ c1w)
{
    const int r0 = blockIdx.x * 8;
    const int t  = threadIdx.x;
    __shared__ float hs[8][HD];
    #pragma unroll
    for (int r = 0; r < 8; r++) hs[r][t] = h[(r0 + r) * HD + t];
    __syncthreads();

    float pa[8], pb[8], ca[8], cb[8];
    #pragma unroll
    for (int r = 0; r < 8; r++) { pa[r]=0.f; pb[r]=0.f; ca[r]=0.f; cb[r]=0.f; }

    for (int k = 0; k < HD; k++) {
        float wea = e1w[k * HD + t];
        float web = e1w[(HD + k) * HD + t];
        float wca = c1w[k * HD + t];
        float wcb = c1w[(HD + k) * HD + t];
        #pragma unroll
        for (int r = 0; r < 8; r++) {
            float hk = hs[r][k];
            pa[r] = fmaf(hk, wea, pa[r]);
            pb[r] = fmaf(hk, web, pb[r]);
            ca[r] = fmaf(hk, wca, ca[r]);
            cb[r] = fmaf(hk, wcb, cb[r]);
        }
    }
    #pragma unroll
    for (int r = 0; r < 8; r++) {
        int bi = r0 + r;
        g_PA[bi * HD + t] = pa[r];
        g_PB[bi * HD + t] = pb[r];
        g_CA[bi * HD + t] = ca[r];
        g_CB[bi * HD + t] = cb[r];
    }
}

// ---------------- kernel 2: pairwise squared distances ---------------------
__global__ void __launch_bounds__(256) dist_kernel(
    const float* __restrict__ x, const float* __restrict__ x0)
{
    int idx = blockIdx.x * 256 + threadIdx.x;
    int j = idx & 255;
    int bi = idx >> 8;
    int b  = bi >> 8;
    const float* xi = x  + bi * 3;
    const float* xj = x  + (b * NPTS + j) * 3;
    float dx = xi[0]-xj[0], dy = xi[1]-xj[1], dz = xi[2]-xj[2];
    g_D2[idx] = dx*dx + dy*dy + dz*dz;
    const float* yi = x0 + bi * 3;
    const float* yj = x0 + (b * NPTS + j) * 3;
    float ex = yi[0]-yj[0], ey = yi[1]-yj[1], ez = yi[2]-yj[2];
    g_D02[idx] = ex*ex + ey*ey + ez*ez;
}

// ============================================================================
// smem layout (bytes):
//   [0      : 17408)   A buffer 0 (hi 8704 | lo 8704)   32 x 136 bf16 each
//   [17408  : 34816)   A buffer 1 (hi | lo)
//   [34816  : 69632)   B hi tile (128 x 136 bf16)
//   [69632  : 104448)  B lo tile
//   [104448 : ...)     ext float scratch
// ============================================================================
#define OFF_BHI  34816
#define OFF_BLO  69632
#define OFF_EXT  104448
#define E_SMEM_TOTAL (OFF_EXT + 1184*4)
#define C_SMEM_TOTAL (OFF_EXT + 992*4)

// producer: warp w -> local rows w*4..w*4+3; lane -> k = lane*4..lane*4+3.
// Writes hi at aBuf, lo at aBuf + ATH_BYTES.
__device__ __forceinline__ void produce_tile(
    int w, int lane, int j0,
    const float4 pab, const float4 w256_4, const float4 w257_4,
    const float* __restrict__ Pbase,
    const float* d2all, const float* d02all,
    uint32_t aBuf)
{
    const int k0 = lane * 4;
    #pragma unroll
    for (int rr = 0; rr < 4; rr++) {
        int row = w * 4 + rr;
        const float4 pb4 = *reinterpret_cast<const float4*>(
            &Pbase[(size_t)(j0 + row) * HD + k0]);
        float dj = d2all[j0 + row], d0j = d02all[j0 + row];
        float v0 = siluf(pab.x + pb4.x + dj * w256_4.x + d0j * w257_4.x);
        float v1 = siluf(pab.y + pb4.y + dj * w256_4.y + d0j * w257_4.y);
        float v2 = siluf(pab.z + pb4.z + dj * w256_4.z + d0j * w257_4.z);
        float v3 = siluf(pab.w + pb4.w + dj * w256_4.w + d0j * w257_4.w);
        __nv_bfloat16 h0 = __float2bfloat16(v0);
        __nv_bfloat16 h1 = __float2bfloat16(v1);
        __nv_bfloat16 h2 = __float2bfloat16(v2);
        __nv_bfloat16 h3 = __float2bfloat16(v3);
        __nv_bfloat162 H01 = __halves2bfloat162(h0, h1);
        __nv_bfloat162 H23 = __halves2bfloat162(h2, h3);
        __nv_bfloat162 L01 = __halves2bfloat162(
            __float2bfloat16(v0 - __bfloat162float(h0)),
            __float2bfloat16(v1 - __bfloat162float(h1)));
        __nv_bfloat162 L23 = __halves2bfloat162(
            __float2bfloat16(v2 - __bfloat162float(h2)),
            __float2bfloat16(v3 - __bfloat162float(h3)));
        uint32_t off = row * (BSTRIDE * 2) + lane * 8;
        asm volatile("st.shared.v2.b32 [%0], {%1, %2};"
            :: "r"(aBuf + off),
               "r"(*reinterpret_cast<uint32_t*>(&H01)),
               "r"(*reinterpret_cast<uint32_t*>(&H23)) : "memory");
        asm volatile("st.shared.v2.b32 [%0], {%1, %2};"
            :: "r"(aBuf + ATH_BYTES + off),
               "r"(*reinterpret_cast<uint32_t*>(&L01)),
               "r"(*reinterpret_cast<uint32_t*>(&L23)) : "memory");
    }
}

// warp GEMM: 3-pass bf16 split; warp tile rows mrow0..+16, cols ncol0..+32.
// acc[4][4]: ni = 8-col group.
__device__ __forceinline__ void gemm_warp(
    float acc[4][4], int mrow0, int ncol0, int lane,
    uint32_t aBuf, uint32_t bHi32, uint32_t bLo32)
{
    uint32_t aoff, boff[2];
    {
        int arow = (lane & 15);
        int akp  = (lane >> 4) * 8;
        aoff = (mrow0 + arow) * (BSTRIDE * 2) + akp * 2;
        int bn = (lane & 7) + ((lane >> 4) & 1) * 8;
        int bkp = ((lane >> 3) & 1) * 8;
        #pragma unroll
        for (int nb = 0; nb < 2; nb++)
            boff[nb] = (ncol0 + nb * 16 + bn) * (BSTRIDE * 2) + bkp * 2;
    }
    #pragma unroll
    for (int ks = 0; ks < 8; ks++) {
        const uint32_t kb = ks * 32;
        uint32_t ah[4], al[4], bh[2][4], bl[2][4];
        ldsm4(ah, aBuf + aoff + kb);
        ldsm4(al, aBuf + ATH_BYTES + aoff + kb);
        #pragma unroll
        for (int nb = 0; nb < 2; nb++) {
            ldsm4(bh[nb], bHi32 + boff[nb] + kb);
            ldsm4(bl[nb], bLo32 + boff[nb] + kb);
        }
        #pragma unroll
        for (int nb = 0; nb < 2; nb++) {
            mma_bf16(acc[2*nb],     ah, bh[nb][0], bh[nb][1]);
            mma_bf16(acc[2*nb + 1], ah, bh[nb][2], bh[nb][3]);
            mma_bf16(acc[2*nb],     ah, bl[nb][0], bl[nb][1]);
            mma_bf16(acc[2*nb + 1], ah, bl[nb][2], bl[nb][3]);
            mma_bf16(acc[2*nb],     al, bh[nb][0], bh[nb][1]);
            mma_bf16(acc[2*nb + 1], al, bh[nb][2], bh[nb][3]);
        }
    }
}

// ---------------- kernel 3: edge chain -> g_agg ----------------------------
// ext floats: d2all[256] d02all[256] b2s[128] eiws[128] dotP[128] e_s[32] aggW[256]
__global__ void __launch_bounds__(256, 2) edge_kernel(
    const float* __restrict__ e1w, const float* __restrict__ e1b,
    const float* __restrict__ e2b,
    const float* __restrict__ eiw, const float* __restrict__ eib)
{
    extern __shared__ __align__(16) unsigned char smem[];
    float* ext    = (float*)(smem + OFF_EXT);
    float* d2all  = ext;         float* d02all = ext + 256;
    float* b2s    = ext + 512;   float* eiws   = ext + 640;
    float* dotP   = ext + 768;   // 4*32
    float* e_s    = ext + 896;   // 32
    float* aggW   = ext + 928;   // 8*32

    const uint32_t smem32 = smem_u32(smem);
    const uint32_t bHi32 = smem32 + OFF_BHI, bLo32 = smem32 + OFF_BLO;

    const int bi = blockIdx.x;
    const int b  = bi >> 8;
    const int i  = bi & 255;
    const int t  = threadIdx.x;
    const int lane = t & 31, w = t >> 5;
    const int s = lane & 3, q = lane >> 2;
    const int mrow0 = (w & 1) * 16, ncol0 = (w >> 1) * 32;

    {
        const uint4* srcH = (const uint4*)g_eBhi;
        const uint4* srcL = (const uint4*)g_eBlo;
        uint4* dstH = (uint4*)(smem + OFF_BHI);
        uint4* dstL = (uint4*)(smem + OFF_BLO);
        for (int idx = t; idx < BT_BYTES/16; idx += 256) {
            dstH[idx] = srcH[idx];
            dstL[idx] = srcL[idx];
        }
    }
    if (t < 128) { b2s[t] = e2b[t]; eiws[t] = eiw[t]; }
    d2all[t]  = g_D2 [bi * NPTS + t];
    d02all[t] = g_D02[bi * NPTS + t];

    const int k0 = lane * 4;
    float4 pab = *reinterpret_cast<const float4*>(&g_PA[bi * HD + k0]);
    const float4 b1_4 = *reinterpret_cast<const float4*>(&e1b[k0]);
    pab.x += b1_4.x; pab.y += b1_4.y; pab.z += b1_4.z; pab.w += b1_4.w;
    const float4 w256_4 = *reinterpret_cast<const float4*>(&e1w[256 * HD + k0]);
    const float4 w257_4 = *reinterpret_cast<const float4*>(&e1w[257 * HD + k0]);
    const float bi0 = eib[0];
    const float* PBb = g_PB + (size_t)b * NPTS * HD;

    float aggacc[8];
    #pragma unroll
    for (int c = 0; c < 8; c++) aggacc[c] = 0.f;

    __syncthreads();
    produce_tile(w, lane, 0, pab, w256_4, w257_4, PBb, d2all, d02all, smem32);
    __syncthreads();

    for (int tile = 0; tile < 8; tile++) {
        const int j0 = tile * JT;
        const uint32_t aBuf = smem32 + (tile & 1) * ABUF_BYTES;
        // produce-ahead: next tile into other buffer (no barrier before GEMM)
        if (tile < 7)
            produce_tile(w, lane, j0 + JT, pab, w256_4, w257_4, PBb,
                         d2all, d02all, smem32 + ((tile + 1) & 1) * ABUF_BYTES);

        float acc[4][4];
        #pragma unroll
        for (int a = 0; a < 4; a++)
            #pragma unroll
            for (int e = 0; e < 4; e++) acc[a][e] = 0.f;
        gemm_warp(acc, mrow0, ncol0, lane, aBuf, bHi32, bLo32);

        // m = silu(D + b2); per-row dots with eiw
        float dot0 = 0.f, dot1 = 0.f;
        #pragma unroll
        for (int ni = 0; ni < 4; ni++) {
            int c0 = ncol0 + ni * 8 + 2 * s;
            float b2a = b2s[c0], b2b = b2s[c0 + 1];
            float* A = acc[ni];
            A[0] = siluf(A[0] + b2a); A[1] = siluf(A[1] + b2b);
            A[2] = siluf(A[2] + b2a); A[3] = siluf(A[3] + b2b);
            float ea = eiws[c0], eb = eiws[c0 + 1];
            dot0 += A[0]*ea + A[1]*eb;
            dot1 += A[2]*ea + A[3]*eb;
        }
        dot0 += __shfl_xor_sync(0xffffffffu, dot0, 1);
        dot0 += __shfl_xor_sync(0xffffffffu, dot0, 2);
        dot1 += __shfl_xor_sync(0xffffffffu, dot1, 1);
        dot1 += __shfl_xor_sync(0xffffffffu, dot1, 2);
        if (s == 0) {
            dotP[(w >> 1) * JT + mrow0 + q]     = dot0;
            dotP[(w >> 1) * JT + mrow0 + q + 8] = dot1;
        }
        __syncthreads();
        if (t < JT) {
            float sv = dotP[t] + dotP[JT + t] + dotP[2*JT + t]
                     + dotP[3*JT + t] + bi0;
            float e = sigm(sv);
            if (j0 + t == i) e = 0.f;
            e_s[t] = e;
        }
        __syncthreads();
        {
            float e0 = e_s[mrow0 + q], e1 = e_s[mrow0 + q + 8];
            #pragma unroll
            for (int ni = 0; ni < 4; ni++) {
                float* A = acc[ni];
                aggacc[ni*2+0] = fmaf(e0, A[0], fmaf(e1, A[2], aggacc[ni*2+0]));
                aggacc[ni*2+1] = fmaf(e0, A[1], fmaf(e1, A[3], aggacc[ni*2+1]));
            }
        }
        // no end barrier needed: next iter's dotP write is preceded by this
        // iter's sync #2, and buffer hazards are separated by >= one barrier.
    }
    // reduce aggacc over q-lanes (cols depend only on s)
    #pragma unroll
    for (int c = 0; c < 8; c++) {
        float v = aggacc[c];
        v += __shfl_xor_sync(0xffffffffu, v, 4);
        v += __shfl_xor_sync(0xffffffffu, v, 8);
        v += __shfl_xor_sync(0xffffffffu, v, 16);
        aggacc[c] = v;
    }
    __syncthreads();
    if (q == 0) {
        #pragma unroll
        for (int ni = 0; ni < 4; ni++) {
            aggW[w * 32 + ni * 8 + 2 * s]     = aggacc[ni*2+0];
            aggW[w * 32 + ni * 8 + 2 * s + 1] = aggacc[ni*2+1];
        }
    }
    __syncthreads();
    if (t < 128) {
        int cq = t >> 5, cl = t & 31;
        float sv = aggW[(2*cq) * 32 + cl] + aggW[(2*cq + 1) * 32 + cl];
        g_agg[bi * HD + t] = sv * (1.0f / 256.0f);
    }
}

// ---------------- kernel 4: coordinate chain -> g_upd ----------------------
// ext floats: d2all[256] d02all[256] b2s[128] c3ws[128] dotP[128] updx/y/z[32]
__global__ void __launch_bounds__(256, 2) cor_kernel(
    const float* __restrict__ c1w, const float* __restrict__ c1b,
    const float* __restrict__ c2b,
    const float* __restrict__ c3w, const float* __restrict__ c3b,
    const float* __restrict__ x)
{
    extern __shared__ __align__(16) unsigned char smem[];
    float* ext    = (float*)(smem + OFF_EXT);
    float* d2all  = ext;         float* d02all = ext + 256;
    float* b2s    = ext + 512;   float* c3ws   = ext + 640;
    float* dotP   = ext + 768;   // 4*32
    float* updx   = ext + 896;   float* updy = ext + 928;  float* updz = ext + 960;

    const uint32_t smem32 = smem_u32(smem);
    const uint32_t bHi32 = smem32 + OFF_BHI, bLo32 = smem32 + OFF_BLO;

    const int bi = blockIdx.x;
    const int b  = bi >> 8;
    const int i  = bi & 255;
    const int t  = threadIdx.x;
    const int lane = t & 31, w = t >> 5;
    const int s = lane & 3, q = lane >> 2;
    const int mrow0 = (w & 1) * 16, ncol0 = (w >> 1) * 32;

    {
        const uint4* srcH = (const uint4*)g_cBhi;
        const uint4* srcL = (const uint4*)g_cBlo;
        uint4* dstH = (uint4*)(smem + OFF_BHI);
        uint4* dstL = (uint4*)(smem + OFF_BLO);
        for (int idx = t; idx < BT_BYTES/16; idx += 256) {
            dstH[idx] = srcH[idx];
            dstL[idx] = srcL[idx];
        }
    }
    if (t < 128) { b2s[t] = c2b[t]; c3ws[t] = c3w[t]; }
    d2all[t]  = g_D2 [bi * NPTS + t];
    d02all[t] = g_D02[bi * NPTS + t];

    const int k0 = lane * 4;
    float4 pab = *reinterpret_cast<const float4*>(&g_CA[bi * HD + k0]);
    const float4 b1_4 = *reinterpret_cast<const float4*>(&c1b[k0]);
    pab.x += b1_4.x; pab.y += b1_4.y; pab.z += b1_4.z; pab.w += b1_4.w;
    const float4 w256_4 = *reinterpret_cast<const float4*>(&c1w[256 * HD + k0]);
    const float4 w257_4 = *reinterpret_cast<const float4*>(&c1w[257 * HD + k0]);
    const float b3 = c3b[0];
    const float* CBb = g_CB + (size_t)b * NPTS * HD;

    const float xi0 = x[bi * 3 + 0];
    const float xi1 = x[bi * 3 + 1];
    const float xi2 = x[bi * 3 + 2];
    float ux = 0.f, uy = 0.f, uz = 0.f;

    __syncthreads();
    produce_tile(w, lane, 0, pab, w256_4, w257_4, CBb, d2all, d02all, smem32);
    __syncthreads();

    for (int tile = 0; tile < 8; tile++) {
        const int j0 = tile * JT;
        const uint32_t aBuf = smem32 + (tile & 1) * ABUF_BYTES;
        if (tile < 7)
            produce_tile(w, lane, j0 + JT, pab, w256_4, w257_4, CBb,
                         d2all, d02all, smem32 + ((tile + 1) & 1) * ABUF_BYTES);

        float acc[4][4];
        #pragma unroll
        for (int a = 0; a < 4; a++)
            #pragma unroll
            for (int e = 0; e < 4; e++) acc[a][e] = 0.f;
        gemm_warp(acc, mrow0, ncol0, lane, aBuf, bHi32, bLo32);

        float dot0 = 0.f, dot1 = 0.f;
        #pragma unroll
        for (int ni = 0; ni < 4; ni++) {
            int c0 = ncol0 + ni * 8 + 2 * s;
            float b2a = b2s[c0], b2b = b2s[c0 + 1];
            float* A = acc[ni];
            float m0 = siluf(A[0] + b2a), m1 = siluf(A[1] + b2b);
            float m2 = siluf(A[2] + b2a), m3 = siluf(A[3] + b2b);
            float wa = c3ws[c0], wb = c3ws[c0 + 1];
            dot0 += m0*wa + m1*wb;
            dot1 += m2*wa + m3*wb;
        }
        dot0 += __shfl_xor_sync(0xffffffffu, dot0, 1);
        dot0 += __shfl_xor_sync(0xffffffffu, dot0, 2);
        dot1 += __shfl_xor_sync(0xffffffffu, dot1, 1);
        dot1 += __shfl_xor_sync(0xffffffffu, dot1, 2);
        if (s == 0) {
            dotP[(w >> 1) * JT + mrow0 + q]     = dot0;
            dotP[(w >> 1) * JT + mrow0 + q + 8] = dot1;
        }
        __syncthreads();
        if (t < JT) {
            int j = j0 + t;
            if (j != i) {
                float cw = dotP[t] + dotP[JT + t] + dotP[2*JT + t]
                         + dotP[3*JT + t] + b3;
                float d2v = d2all[j];
                float dist = (d2v > 0.f) ? sqrtf(d2v) : 0.f;
                float f = __fdividef(cw, dist + 1.f);
                const float* xj = x + ((size_t)b * NPTS + j) * 3;
                ux = fmaf(f, xi0 - xj[0], ux);
                uy = fmaf(f, xi1 - xj[1], uy);
                uz = fmaf(f, xi2 - xj[2], uz);
            }
        }
        __syncthreads();   // protect dotP from next iter's writes
    }
    if (t < JT) { updx[t] = ux; updy[t] = uy; updz[t] = uz; }
    __syncthreads();
    if (t < 3) {
        const float* arr = (t == 0) ? updx : (t == 1) ? updy : updz;
        float sv = 0.f;
        for (int r = 0; r < JT; r++) sv += arr[r];
        g_upd[bi * 3 + t] = sv * (1.0f / 256.0f);
    }
}

// ---------------- kernel 5: node MLP + outputs -----------------------------
__global__ void __launch_bounds__(128) final_kernel(
    const float* __restrict__ hin, const float* __restrict__ xin,
    const float* __restrict__ pm,
    const float* __restrict__ n1w, const float* __restrict__ n1b,
    const float* __restrict__ n2w, const float* __restrict__ n2b,
    float* __restrict__ out)
{
    const int r0 = blockIdx.x * 8;
    const int t  = threadIdx.x;
    __shared__ float nin[8][256];
    __shared__ float tmid[8][HD];
    #pragma unroll
    for (int r = 0; r < 8; r++) {
        nin[r][t]       = hin[(r0 + r) * HD + t];
        nin[r][HD + t]  = g_agg[(r0 + r) * HD + t];
    }
    __syncthreads();
    float a[8];
    #pragma unroll
    for (int r = 0; r < 8; r++) a[r] = n1b[t];
    for (int k = 0; k < 256; k++) {
        float wv = n1w[k * HD + t];
        #pragma unroll
        for (int r = 0; r < 8; r++) a[r] = fmaf(nin[r][k], wv, a[r]);
    }
    #pragma unroll
    for (int r = 0; r < 8; r++) tmid[r][t] = siluf(a[r]);
    __syncthreads();
    #pragma unroll
    for (int r = 0; r < 8; r++) a[r] = n2b[t];
    for (int k = 0; k < HD; k++) {
        float wv = n2w[k * HD + t];
        #pragma unroll
        for (int r = 0; r < 8; r++) a[r] = fmaf(tmid[r][k], wv, a[r]);
    }
    float* outx = out;                  // x_next: BN*3
    float* outh = out + BN * 3;         // h_next: BN*HD
    #pragma unroll
    for (int r = 0; r < 8; r++) {
        int bi = r0 + r;
        float mask = pm[bi];
        outh[bi * HD + t] = (nin[r][t] + a[r]) * mask;
        if (t < 3) outx[bi * 3 + t] = (xin[bi * 3 + t] + g_upd[bi * 3 + t]) * mask;
    }
}

// ---------------- launch ----------------------------------------------------
extern "C" void kernel_launch(void* const* d_in, const int* in_sizes, int n_in,
                              void* d_out, int out_size)
{
    const float* x   = (const float*)d_in[0];
    const float* h   = (const float*)d_in[1];
    const float* x0  = (const float*)d_in[2];
    const float* pm  = (const float*)d_in[3];
    const float* e1w = (const float*)d_in[4];
    const float* e1b = (const float*)d_in[5];
    const float* e2w = (const float*)d_in[6];
    const float* e2b = (const float*)d_in[7];
    const float* eiw = (const float*)d_in[8];
    const float* eib = (const float*)d_in[9];
    const float* n1w = (const float*)d_in[10];
    const float* n1b = (const float*)d_in[11];
    const float* n2w = (const float*)d_in[12];
    const float* n2b = (const float*)d_in[13];
    const float* c1w = (const float*)d_in[14];
    const float* c1b = (const float*)d_in[15];
    const float* c2w = (const float*)d_in[16];
    const float* c2b = (const float*)d_in[17];
    const float* c3w = (const float*)d_in[18];
    const float* c3b = (const float*)d_in[19];
    float* out = (float*)d_out;

    cudaFuncSetAttribute(edge_kernel,
        cudaFuncAttributeMaxDynamicSharedMemorySize, E_SMEM_TOTAL);
    cudaFuncSetAttribute(cor_kernel,
        cudaFuncAttributeMaxDynamicSharedMemorySize, C_SMEM_TOTAL);

    prep_kernel<<<128, 128>>>(e2w, c2w);
    proj_kernel<<<BN / 8, 128>>>(h, e1w, c1w);
    dist_kernel<<<(BN * NPTS) / 256, 256>>>(x, x0);
    edge_kernel<<<BN, 256, E_SMEM_TOTAL>>>(e1w, e1b, e2b, eiw, eib);
    cor_kernel<<<BN, 256, C_SMEM_TOTAL>>>(c1w, c1b, c2b, c3w, c3b, x);
    final_kernel<<<BN / 8, 128>>>(h, x, pm, n1w, n1b, n2w, n2b, out);
}